// round 12
// baseline (speedup 1.0000x reference)
#include <cuda_runtime.h>
#include <math.h>
#include <stdint.h>

#define BATCH 4
#define SEQ   1024
#define DM    1024
#define NH    16
#define HD    64
#define BH    (BATCH*NH)   // 64
#define NREL  33
#define NEGV  (-1e6f)
#define SCALE 0.1803368801111243f   // (1/sqrt(64)) * log2(e)

// ---------------- scratch (device globals: allocation is forbidden) ----------
__device__ float g_Q[BH*SEQ*HD];                 // [bh][s][d]  (tf32-rounded)
__device__ float g_K[BH*SEQ*HD];
__device__ float g_V[BH*SEQ*HD];
__device__ float g_ctx[BATCH*SEQ*DM];            // merged-head ctx (tf32-rounded)
__device__ float g_rw [4u*1024*1024];            // pre-rounded Wq,Wk,Wv,Wo

// ---------------- helpers ----------------------------------------------------
__device__ __forceinline__ uint32_t f2tf(float f) {
    uint32_t u;
    asm("cvt.rna.tf32.f32 %0, %1;" : "=r"(u) : "f"(f));
    return u;
}
__device__ __forceinline__ float f2tf_f(float f) {
    return __uint_as_float(f2tf(f));
}
__device__ __forceinline__ uint32_t f2tf_u(uint32_t raw) {  // round raw fp32 bits
    uint32_t u;
    asm("cvt.rna.tf32.f32 %0, %1;" : "=r"(u) : "f"(__uint_as_float(raw)));
    return u;
}
__device__ __forceinline__ void mma8(float* c,
    uint32_t a0, uint32_t a1, uint32_t a2, uint32_t a3,
    uint32_t b0, uint32_t b1)
{
    asm volatile(
        "mma.sync.aligned.m16n8k8.row.col.f32.tf32.tf32.f32 "
        "{%0,%1,%2,%3}, {%4,%5,%6,%7}, {%8,%9}, {%0,%1,%2,%3};"
        : "+f"(c[0]), "+f"(c[1]), "+f"(c[2]), "+f"(c[3])
        : "r"(a0), "r"(a1), "r"(a2), "r"(a3), "r"(b0), "r"(b1));
}
__device__ __forceinline__ void ldsm4(uint32_t& r0, uint32_t& r1,
                                      uint32_t& r2, uint32_t& r3, uint32_t addr)
{
    asm volatile("ldmatrix.sync.aligned.m8n8.x4.shared.b16 {%0,%1,%2,%3}, [%4];"
        : "=r"(r0), "=r"(r1), "=r"(r2), "=r"(r3) : "r"(addr));
}
__device__ __forceinline__ void cp16(void* smem_dst, const void* gmem_src) {
    uint32_t s = (uint32_t)__cvta_generic_to_shared(smem_dst);
    asm volatile("cp.async.cg.shared.global [%0], [%1], 16;\n"
                 :: "r"(s), "l"(gmem_src));
}
__device__ __forceinline__ void cp_commit() {
    asm volatile("cp.async.commit_group;\n");
}
template<int N>
__device__ __forceinline__ void cp_wait() {
    asm volatile("cp.async.wait_group %0;\n" :: "n"(N));
}
__device__ __forceinline__ uint32_t ldu(const float* p) {
    return __float_as_uint(*p);
}
__device__ __forceinline__ uint32_t smem_u32(const void* p) {
    return (uint32_t)__cvta_generic_to_shared(p);
}

// =============================================================================
// fp32 -> tf32-rounded fp32 copies (weights only, 4 regions)
// =============================================================================
struct ConvArgs {
    const float* src[4];
    float* dst[4];
    int n4;
};
__global__ void __launch_bounds__(256) conv_kernel(ConvArgs a)
{
    int rg = blockIdx.y;
    const float4* s = reinterpret_cast<const float4*>(a.src[rg]);
    float4* d = reinterpret_cast<float4*>(a.dst[rg]);
    for (int i = blockIdx.x * 256 + threadIdx.x; i < a.n4; i += gridDim.x * 256) {
        float4 v = s[i];
        v.x = f2tf_f(v.x); v.y = f2tf_f(v.y);
        v.z = f2tf_f(v.z); v.w = f2tf_f(v.w);
        d[i] = v;
    }
}

struct Proj3Args {
    const float* A[3];
    const float* B[3];
    float*       C[3];
};

// =============================================================================
// Big NT GEMM: C = A * B^T. B pre-rounded; A rounded post-ldmatrix iff CVT_A.
// 128x128 tile, 128 threads, warp tile 64x64, ldmatrix fragments, 3 CTAs/SM.
// =============================================================================
template<bool PROJ3, bool CVT_A>
__global__ void __launch_bounds__(128, 3)
gemm_big(Proj3Args args, int M, int N, int K)
{
    constexpr int BM = 128, BN = 128, BK = 32, T = 128;
    constexpr int ASZ = BM * (BK + 4);
    constexpr int BSZ = BN * (BK + 4);
    constexpr int ABYTES = ASZ * 4;
    constexpr int BBYTES = BSZ * 4;

    extern __shared__ float dynsmem[];
    float (*As)[BM][BK + 4] = reinterpret_cast<float(*)[BM][BK + 4]>(dynsmem);
    float (*Bs)[BN][BK + 4] = reinterpret_cast<float(*)[BN][BK + 4]>(dynsmem + 2 * ASZ);

    int z = PROJ3 ? blockIdx.z : 0;
    const float* A = args.A[z];
    const float* B = args.B[z];
    float*       C = args.C[z];

    int m0  = blockIdx.y * BM, n0 = blockIdx.x * BN;
    int tid = threadIdx.x;
    int lane = tid & 31, warp = tid >> 5;
    int gid = lane >> 2, tig = lane & 3;
    int wm0 = (warp >> 1) * 64;
    int wn0 = (warp & 1) * 64;

    int Lm = lane >> 3, Lr = lane & 7;
    int a_row = ((Lm & 1) ? 8 : 0) + Lr;
    int a_col = (Lm & 2) ? 4 : 0;
    int b_row = ((Lm & 2) ? 8 : 0) + Lr;
    int b_col = (Lm & 1) ? 4 : 0;

    uint32_t sA = smem_u32(&As[0][0][0]);
    uint32_t sB = smem_u32(&Bs[0][0][0]);
    uint32_t aBase[4], bBase[4];
    #pragma unroll
    for (int mt = 0; mt < 4; mt++)
        aBase[mt] = sA + ((wm0 + mt * 16 + a_row) * (BK + 4) + a_col) * 4;
    #pragma unroll
    for (int np = 0; np < 4; np++)
        bBase[np] = sB + ((wn0 + np * 16 + b_row) * (BK + 4) + b_col) * 4;

    auto load_tiles = [&](int buf, int k0) {
        #pragma unroll
        for (int it = 0; it < 8; it++) {
            int idx = tid + it * T;
            int row = idx >> 3, kq = (idx & 7) << 2;
            cp16(&As[buf][row][kq], &A[(size_t)(m0 + row) * K + k0 + kq]);
        }
        #pragma unroll
        for (int it = 0; it < 8; it++) {
            int idx = tid + it * T;
            int row = idx >> 3, kq = (idx & 7) << 2;
            cp16(&Bs[buf][row][kq], &B[(size_t)(n0 + row) * K + k0 + kq]);
        }
        cp_commit();
    };

    float acc[4][8][4];
    #pragma unroll
    for (int i = 0; i < 4; i++)
        #pragma unroll
        for (int j = 0; j < 8; j++)
            #pragma unroll
            for (int l = 0; l < 4; l++) acc[i][j][l] = 0.f;

    const int KT = K / BK;
    load_tiles(0, 0);

    for (int kt = 0; kt < KT; kt++) {
        int buf = kt & 1;
        if (kt + 1 < KT) { load_tiles(buf ^ 1, (kt + 1) * BK); cp_wait<1>(); }
        else             { cp_wait<0>(); }
        __syncthreads();

        uint32_t aOff = buf * ABYTES;
        uint32_t bOff = buf * BBYTES;
        #pragma unroll
        for (int kc = 0; kc < BK / 8; kc++) {
            uint32_t kb4 = kc * 32;
            uint32_t af[4][4];
            #pragma unroll
            for (int mt = 0; mt < 4; mt++) {
                ldsm4(af[mt][0], af[mt][1], af[mt][2], af[mt][3],
                      aBase[mt] + aOff + kb4);
                if (CVT_A) {
                    af[mt][0] = f2tf_u(af[mt][0]);
                    af[mt][1] = f2tf_u(af[mt][1]);
                    af[mt][2] = f2tf_u(af[mt][2]);
                    af[mt][3] = f2tf_u(af[mt][3]);
                }
            }
            uint32_t bf[8][2];
            #pragma unroll
            for (int np = 0; np < 4; np++)
                ldsm4(bf[2*np][0], bf[2*np][1], bf[2*np+1][0], bf[2*np+1][1],
                      bBase[np] + bOff + kb4);
            #pragma unroll
            for (int mt = 0; mt < 4; mt++)
                #pragma unroll
                for (int nt = 0; nt < 8; nt++)
                    mma8(acc[mt][nt], af[mt][0], af[mt][1], af[mt][2], af[mt][3],
                         bf[nt][0], bf[nt][1]);
        }
        __syncthreads();
    }

    #pragma unroll
    for (int mt = 0; mt < 4; mt++) {
        #pragma unroll
        for (int nt = 0; nt < 8; nt++) {
            int r0 = m0 + wm0 + mt * 16 + gid;
            int c0 = n0 + wn0 + nt * 8 + 2 * tig;
            if (PROJ3) {
                float2 t0 = make_float2(f2tf_f(acc[mt][nt][0]), f2tf_f(acc[mt][nt][1]));
                float2 t1 = make_float2(f2tf_f(acc[mt][nt][2]), f2tf_f(acc[mt][nt][3]));
                int b = r0 >> 10, s = r0 & 1023, h = c0 >> 6, d = c0 & 63;
                *reinterpret_cast<float2*>(
                    &C[(size_t)((b * NH + h) * SEQ + s) * HD + d]) = t0;
                int b2 = (r0 + 8) >> 10, s2 = (r0 + 8) & 1023;
                *reinterpret_cast<float2*>(
                    &C[(size_t)((b2 * NH + h) * SEQ + s2) * HD + d]) = t1;
            } else {
                float2 t0 = make_float2(acc[mt][nt][0], acc[mt][nt][1]);
                float2 t1 = make_float2(acc[mt][nt][2], acc[mt][nt][3]);
                *reinterpret_cast<float2*>(&C[(size_t)r0 * N + c0]) = t0;
                *reinterpret_cast<float2*>(&C[(size_t)(r0 + 8) * N + c0]) = t1;
            }
        }
    }
}

// =============================================================================
// Fused flash attention (shuffle-P, single-buffered V, ldmatrix K fragments).
// =============================================================================
__global__ void __launch_bounds__(128, 3)
flash_kernel(const int* __restrict__ valid_lens,
             const float* __restrict__ Ek, const float* __restrict__ Ev)
{
    constexpr int KS = 68;
    constexpr int TILE = 64 * KS;
    constexpr int TILEB = TILE * 4;

    extern __shared__ float sm[];
    float* Ks = sm;                 // [2][64][68]
    float* Vs = Ks + 2 * TILE;      // [64][68]  (also Ek/Ev staging)
    float* SQ = Vs + TILE;          // [64][33]
    float* SMID = SQ + 64 * NREL;   // [64][33]
    float* MR = SMID + 64 * NREL;   // [64]
    float* IL = MR + 64;            // [64]

    const int q0 = blockIdx.x * 64;
    const int bh = blockIdx.y;
    const int vl  = valid_lens[bh >> 4];
    const int vlc = (vl + 63) & ~63;

    const int tid = threadIdx.x;
    const int lane = tid & 31, warp = tid >> 5;
    const int gid = lane >> 2, tig = lane & 3;
    const int wq = warp * 16;

    int Lm = lane >> 3, Lr = lane & 7;
    int b_row = ((Lm & 2) ? 8 : 0) + Lr;
    int b_col = (Lm & 1) ? 4 : 0;
    uint32_t sK = smem_u32(Ks);
    uint32_t kBase[4];
    #pragma unroll
    for (int np = 0; np < 4; np++)
        kBase[np] = sK + ((np * 16 + b_row) * KS + b_col) * 4;

    auto loadK = [&](int buf, int k0) {
        const float* Kg = g_K + ((size_t)bh * SEQ + k0) * HD;
        #pragma unroll
        for (int it = 0; it < 8; it++) {
            int idx = tid + it * 128;
            int row = idx >> 4, c4 = (idx & 15) << 2;
            cp16(&Ks[buf * TILE + row * KS + c4], Kg + row * HD + c4);
        }
        cp_commit();
    };
    auto loadV = [&](int k0) {
        const float* Vg = g_V + ((size_t)bh * SEQ + k0) * HD;
        #pragma unroll
        for (int it = 0; it < 8; it++) {
            int idx = tid + it * 128;
            int row = idx >> 4, c4 = (idx & 15) << 2;
            cp16(&Vs[row * KS + c4], Vg + row * HD + c4);
        }
        cp_commit();
    };

    loadK(0, 0);

    for (int i = tid; i < NREL * 16; i += 128) {
        int row = i >> 4, c = i & 15;
        *reinterpret_cast<float4*>(&Vs[row * KS + 4 * c]) =
            reinterpret_cast<const float4*>(Ek)[i];
    }

    uint32_t qa[8][4];
    {
        const float* Qg = g_Q + ((size_t)bh * SEQ + q0 + wq) * HD;
        #pragma unroll
        for (int kc = 0; kc < 8; kc++) {
            qa[kc][0] = ldu(&Qg[(size_t)gid       * HD + kc * 8 + tig]);
            qa[kc][1] = ldu(&Qg[(size_t)(gid + 8) * HD + kc * 8 + tig]);
            qa[kc][2] = ldu(&Qg[(size_t)gid       * HD + kc * 8 + tig + 4]);
            qa[kc][3] = ldu(&Qg[(size_t)(gid + 8) * HD + kc * 8 + tig + 4]);
        }
    }
    __syncthreads();

    {
        float sq[5][4];
        #pragma unroll
        for (int nt = 0; nt < 5; nt++)
            #pragma unroll
            for (int e = 0; e < 4; e++) sq[nt][e] = 0.f;
        #pragma unroll
        for (int kc = 0; kc < 8; kc++) {
            #pragma unroll
            for (int nt = 0; nt < 5; nt++) {
                uint32_t b0 = f2tf(Vs[(nt * 8 + gid) * KS + kc * 8 + tig]);
                uint32_t b1 = f2tf(Vs[(nt * 8 + gid) * KS + kc * 8 + tig + 4]);
                mma8(sq[nt], qa[kc][0], qa[kc][1], qa[kc][2], qa[kc][3], b0, b1);
            }
        }
        #pragma unroll
        for (int nt = 0; nt < 5; nt++) {
            #pragma unroll
            for (int e = 0; e < 4; e++) {
                int col = nt * 8 + 2 * tig + (e & 1);
                int row = wq + gid + ((e < 2) ? 0 : 8);
                if (col < NREL) SQ[row * NREL + col] = sq[nt][e];
            }
        }
    }
    for (int i = tid; i < 64 * NREL; i += 128) SMID[i] = NEGV;
    __syncthreads();

    const int qrow0 = q0 + wq + gid;
    const int qrow1 = qrow0 + 8;

    float oa[8][4];
    #pragma unroll
    for (int nt = 0; nt < 8; nt++)
        #pragma unroll
        for (int j = 0; j < 4; j++) oa[nt][j] = 0.f;

    float m0 = -1e30f, m1 = -1e30f;
    float l0 = 0.f, l1 = 0.f;
    float eL0 = 0.f, eL1 = 0.f, eH0 = 0.f, eH1 = 0.f;

    const int KT = vlc / 64;
    for (int t = 0; t < KT; t++) {
        int buf = t & 1;
        int k0 = t * 64;
        loadV(k0);
        if (t + 1 < KT) { loadK(buf ^ 1, k0 + 64); cp_wait<2>(); }
        else            { cp_wait<1>(); }
        __syncthreads();

        float sa[8][4];
        #pragma unroll
        for (int nt = 0; nt < 8; nt++)
            #pragma unroll
            for (int j = 0; j < 4; j++) sa[nt][j] = 0.f;

        uint32_t kOff = buf * TILEB;
        #pragma unroll
        for (int kc = 0; kc < 8; kc++) {
            uint32_t bf[8][2];
            #pragma unroll
            for (int np = 0; np < 4; np++)
                ldsm4(bf[2*np][0], bf[2*np][1], bf[2*np+1][0], bf[2*np+1][1],
                      kBase[np] + kOff + kc * 32);
            #pragma unroll
            for (int nt = 0; nt < 8; nt++)
                mma8(sa[nt], qa[kc][0], qa[kc][1], qa[kc][2], qa[kc][3],
                     bf[nt][0], bf[nt][1]);
        }

        float tm0 = -1e30f, tm1 = -1e30f;
        #pragma unroll
        for (int nt = 0; nt < 8; nt++) {
            int kc0 = k0 + nt * 8 + 2 * tig;
            #pragma unroll
            for (int e = 0; e < 4; e++) {
                int kcol = kc0 + (e & 1);
                int qrow = (e < 2) ? qrow0 : qrow1;
                int rloc = wq + gid + ((e < 2) ? 0 : 8);
                int d = kcol - qrow;
                int bidx = min(16, max(-16, d)) + 16;
                float s = (sa[nt][e] + SQ[rloc * NREL + bidx]) * SCALE;
                if (kcol >= vl) s = NEGV;
                sa[nt][e] = s;
                if (d > -16 && d < 16) SMID[rloc * NREL + bidx] = s;
                if (e < 2) tm0 = fmaxf(tm0, s); else tm1 = fmaxf(tm1, s);
            }
        }
        tm0 = fmaxf(tm0, __shfl_xor_sync(0xffffffffu, tm0, 1));
        tm0 = fmaxf(tm0, __shfl_xor_sync(0xffffffffu, tm0, 2));
        tm1 = fmaxf(tm1, __shfl_xor_sync(0xffffffffu, tm1, 1));
        tm1 = fmaxf(tm1, __shfl_xor_sync(0xffffffffu, tm1, 2));

        float mn0 = fmaxf(m0, tm0), mn1 = fmaxf(m1, tm1);
        float a0 = exp2f(m0 - mn0), a1 = exp2f(m1 - mn1);
        m0 = mn0; m1 = mn1;

        float ps0 = 0.f, ps1 = 0.f, tl0 = 0.f, tl1 = 0.f, th0 = 0.f, th1 = 0.f;
        #pragma unroll
        for (int nt = 0; nt < 8; nt++) {
            int kc0 = k0 + nt * 8 + 2 * tig;
            #pragma unroll
            for (int e = 0; e < 4; e++) {
                int kcol = kc0 + (e & 1);
                float p = exp2f(sa[nt][e] - ((e < 2) ? mn0 : mn1));
                sa[nt][e] = p;
                int d = kcol - ((e < 2) ? qrow0 : qrow1);
                if (e < 2) {
                    ps0 += p;
                    if (d <= -16) tl0 += p; else if (d >= 16) th0 += p;
                } else {
                    ps1 += p;
                    if (d <= -16) tl1 += p; else if (d >= 16) th1 += p;
                }
            }
        }
        ps0 += __shfl_xor_sync(0xffffffffu, ps0, 1); ps0 += __shfl_xor_sync(0xffffffffu, ps0, 2);
        ps1 += __shfl_xor_sync(0xffffffffu, ps1, 1); ps1 += __shfl_xor_sync(0xffffffffu, ps1, 2);
        tl0 += __shfl_xor_sync(0xffffffffu, tl0, 1); tl0 += __shfl_xor_sync(0xffffffffu, tl0, 2);
        tl1 += __shfl_xor_sync(0xffffffffu, tl1, 1); tl1 += __shfl_xor_sync(0xffffffffu, tl1, 2);
        th0 += __shfl_xor_sync(0xffffffffu, th0, 1); th0 += __shfl_xor_sync(0xffffffffu, th0, 2);
        th1 += __shfl_xor_sync(0xffffffffu, th1, 1); th1 += __shfl_xor_sync(0xffffffffu, th1, 2);

        l0 = l0 * a0 + ps0;  l1 = l1 * a1 + ps1;
        eL0 = eL0 * a0 + tl0; eL1 = eL1 * a1 + tl1;
        eH0 = eH0 * a0 + th0; eH1 = eH1 * a1 + th1;

        #pragma unroll
        for (int nt = 0; nt < 8; nt++) {
            oa[nt][0] *= a0; oa[nt][1] *= a0;
            oa[nt][2] *= a1; oa[nt][3] *= a1;
        }

        if (t + 1 < KT) cp_wait<1>(); else cp_wait<0>();
        __syncthreads();    // V(t) visible

        const int L0 = (gid << 2) + (tig >> 1);
        const int L1 = L0 + 2;
        const bool odd = (tig & 1) != 0;
        #pragma unroll
        for (int kc = 0; kc < 8; kc++) {
            float a0e = __shfl_sync(0xffffffffu, sa[kc][0], L0);
            float a0o = __shfl_sync(0xffffffffu, sa[kc][1], L0);
            float a1e = __shfl_sync(0xffffffffu, sa[kc][2], L0);
            float a1o = __shfl_sync(0xffffffffu, sa[kc][3], L0);
            float a2e = __shfl_sync(0xffffffffu, sa[kc][0], L1);
            float a2o = __shfl_sync(0xffffffffu, sa[kc][1], L1);
            float a3e = __shfl_sync(0xffffffffu, sa[kc][2], L1);
            float a3o = __shfl_sync(0xffffffffu, sa[kc][3], L1);
            uint32_t p0 = f2tf(odd ? a0o : a0e);
            uint32_t p1 = f2tf(odd ? a1o : a1e);
            uint32_t p2 = f2tf(odd ? a2o : a2e);
            uint32_t p3 = f2tf(odd ? a3o : a3e);
            #pragma unroll
            for (int nt = 0; nt < 8; nt++) {
                uint32_t b0 = ldu(&Vs[(kc * 8 + tig)     * KS + nt * 8 + gid]);
                uint32_t b1 = ldu(&Vs[(kc * 8 + tig + 4) * KS + nt * 8 + gid]);
                mma8(oa[nt], p0, p1, p2, p3, b0, b1);
            }
        }
        __syncthreads();
    }

    // ---- epilogue ----
    const int b = bh >> 4, h = bh & 15;
    float il0 = 1.f / l0, il1 = 1.f / l1;

    if (tig == 0) {
        MR[wq + gid] = m0;     IL[wq + gid] = il0;
        MR[wq + gid + 8] = m1; IL[wq + gid + 8] = il1;
        SQ[(wq + gid) * NREL + 0]      = eL0 * il0;
        SQ[(wq + gid) * NREL + 32]     = eH0 * il0;
        SQ[(wq + gid + 8) * NREL + 0]  = eL1 * il1;
        SQ[(wq + gid + 8) * NREL + 32] = eH1 * il1;
    }
    for (int i = tid; i < NREL * 16; i += 128) {
        int row = i >> 4, c = i & 15;
        *reinterpret_cast<float4*>(&Vs[row * KS + 4 * c]) =
            reinterpret_cast<const float4*>(Ev)[i];
    }
    __syncthreads();

    for (int i = tid; i < 64 * 31; i += 128) {
        int row = i / 31, r = i % 31 + 1;
        SQ[row * NREL + r] = exp2f(SMID[row * NREL + r] - MR[row]) * IL[row];
    }
    __syncthreads();

    #pragma unroll
    for (int nt = 0; nt < 8; nt++) {
        oa[nt][0] *= il0; oa[nt][1] *= il0;
        oa[nt][2] *= il1; oa[nt][3] *= il1;
    }
    for (int r = 0; r < NREL; r++) {
        float pr0 = SQ[(wq + gid) * NREL + r];
        float pr1 = SQ[(wq + gid + 8) * NREL + r];
        #pragma unroll
        for (int nt = 0; nt < 8; nt++) {
            float2 ev = *reinterpret_cast<const float2*>(&Vs[r * KS + nt * 8 + 2 * tig]);
            oa[nt][0] += pr0 * ev.x; oa[nt][1] += pr0 * ev.y;
            oa[nt][2] += pr1 * ev.x; oa[nt][3] += pr1 * ev.y;
        }
    }
    #pragma unroll
    for (int nt = 0; nt < 8; nt++) {
        int col = h * HD + nt * 8 + 2 * tig;
        *reinterpret_cast<float2*>(&g_ctx[(size_t)(b * SEQ + qrow0) * DM + col]) =
            make_float2(f2tf_f(oa[nt][0]), f2tf_f(oa[nt][1]));
        *reinterpret_cast<float2*>(&g_ctx[(size_t)(b * SEQ + qrow1) * DM + col]) =
            make_float2(f2tf_f(oa[nt][2]), f2tf_f(oa[nt][3]));
    }
}

// ---------------- launch ------------------------------------------------------
extern "C" void kernel_launch(void* const* d_in, const int* in_sizes, int n_in,
                              void* d_out, int out_size)
{
    const float* queries = (const float*)d_in[0];
    const float* keys    = (const float*)d_in[1];
    const float* values  = (const float*)d_in[2];
    const int*   valid   = (const int*)  d_in[3];
    const float* Wq      = (const float*)d_in[4];
    const float* Wk      = (const float*)d_in[5];
    const float* Wv      = (const float*)d_in[6];
    const float* Wo      = (const float*)d_in[7];
    const float* Ek      = (const float*)d_in[8];
    const float* Ev      = (const float*)d_in[9];
    float* out = (float*)d_out;

    float *Qp, *Kp, *Vp, *Cp, *rw;
    cudaGetSymbolAddress((void**)&Qp, g_Q);
    cudaGetSymbolAddress((void**)&Kp, g_K);
    cudaGetSymbolAddress((void**)&Vp, g_V);
    cudaGetSymbolAddress((void**)&Cp, g_ctx);
    cudaGetSymbolAddress((void**)&rw, g_rw);

    const int M = BATCH * SEQ;          // 4096
    const size_t WN = (size_t)DM * DM;  // 1M

    const int smBig   = 2 * (128 * 36 + 128 * 36) * sizeof(float);   // 73728
    const int smFlash = (2 * 64 * 68 + 64 * 68
                         + 64 * NREL + 64 * NREL + 128) * sizeof(float); // 69632

    cudaFuncSetAttribute(gemm_big<true, true>,
        cudaFuncAttributeMaxDynamicSharedMemorySize, smBig);
    cudaFuncSetAttribute(gemm_big<false, false>,
        cudaFuncAttributeMaxDynamicSharedMemorySize, smBig);
    cudaFuncSetAttribute(flash_kernel,
        cudaFuncAttributeMaxDynamicSharedMemorySize, smFlash);

    // 1) pre-round WEIGHTS only (16 MB; inputs rounded in-register in proj3)
    ConvArgs ca;
    ca.src[0] = Wq; ca.src[1] = Wk; ca.src[2] = Wv; ca.src[3] = Wo;
    for (int i = 0; i < 4; i++) ca.dst[i] = rw + i * WN;
    ca.n4 = (int)(WN / 4);
    conv_kernel<<<dim3(128, 4), 256>>>(ca);

    // 2) Q/K/V projections: raw inputs as A (rounded post-ldmatrix),
    //    pre-rounded weights as B; head-split + tf32-round store
    Proj3Args pa;
    pa.A[0] = queries;      pa.A[1] = keys;         pa.A[2] = values;
    pa.B[0] = rw;           pa.B[1] = rw + WN;      pa.B[2] = rw + 2 * WN;
    pa.C[0] = Qp;           pa.C[1] = Kp;           pa.C[2] = Vp;
    gemm_big<true, true><<<dim3(DM / 128, M / 128, 3), 128, smBig>>>(pa, M, DM, DM);

    // 3) fused attention
    flash_kernel<<<dim3(SEQ / 64, BH), 128, smFlash>>>(valid, Ek, Ev);

    // 4) out = ctx @ Wo^T (ctx pre-rounded by flash epilogue -> cvt-free)
    Proj3Args po;
    po.A[0] = Cp; po.B[0] = rw + 3 * WN; po.C[0] = out;
    po.A[1] = po.A[2] = Cp; po.B[1] = po.B[2] = rw; po.C[1] = po.C[2] = out;
    gemm_big<false, false><<<dim3(DM / 128, M / 128, 1), 128, smBig>>>(po, M, DM, DM);
}

// round 13
// speedup vs baseline: 1.3136x; 1.3136x over previous
#include <cuda_runtime.h>
#include <math.h>
#include <stdint.h>

#define BATCH 4
#define SEQ   1024
#define DM    1024
#define NH    16
#define HD    64
#define BH    (BATCH*NH)   // 64
#define NREL  33
#define NEGV  (-1e6f)
#define SCALE 0.1803368801111243f   // (1/sqrt(64)) * log2(e)

// ---------------- scratch (device globals: allocation is forbidden) ----------
__device__ float g_Q[BH*SEQ*HD];                 // [bh][s][d]  (tf32-rounded)
__device__ float g_K[BH*SEQ*HD];
__device__ float g_V[BH*SEQ*HD];
__device__ float g_ctx[BATCH*SEQ*DM];            // merged-head ctx (tf32-rounded)
__device__ float g_rw [4u*1024*1024];            // pre-rounded Wq,Wk,Wv,Wo

// ---------------- helpers ----------------------------------------------------
__device__ __forceinline__ uint32_t f2tf(float f) {
    uint32_t u;
    asm("cvt.rna.tf32.f32 %0, %1;" : "=r"(u) : "f"(f));
    return u;
}
__device__ __forceinline__ float f2tf_f(float f) {
    return __uint_as_float(f2tf(f));
}
__device__ __forceinline__ uint32_t f2tf_u(uint32_t raw) {  // round raw fp32 bits
    uint32_t u;
    asm("cvt.rna.tf32.f32 %0, %1;" : "=r"(u) : "f"(__uint_as_float(raw)));
    return u;
}
__device__ __forceinline__ void mma8(float* c,
    uint32_t a0, uint32_t a1, uint32_t a2, uint32_t a3,
    uint32_t b0, uint32_t b1)
{
    asm volatile(
        "mma.sync.aligned.m16n8k8.row.col.f32.tf32.tf32.f32 "
        "{%0,%1,%2,%3}, {%4,%5,%6,%7}, {%8,%9}, {%0,%1,%2,%3};"
        : "+f"(c[0]), "+f"(c[1]), "+f"(c[2]), "+f"(c[3])
        : "r"(a0), "r"(a1), "r"(a2), "r"(a3), "r"(b0), "r"(b1));
}
__device__ __forceinline__ void ldsm4(uint32_t& r0, uint32_t& r1,
                                      uint32_t& r2, uint32_t& r3, uint32_t addr)
{
    asm volatile("ldmatrix.sync.aligned.m8n8.x4.shared.b16 {%0,%1,%2,%3}, [%4];"
        : "=r"(r0), "=r"(r1), "=r"(r2), "=r"(r3) : "r"(addr));
}
__device__ __forceinline__ void cp16(void* smem_dst, const void* gmem_src) {
    uint32_t s = (uint32_t)__cvta_generic_to_shared(smem_dst);
    asm volatile("cp.async.cg.shared.global [%0], [%1], 16;\n"
                 :: "r"(s), "l"(gmem_src));
}
__device__ __forceinline__ void cp_commit() {
    asm volatile("cp.async.commit_group;\n");
}
template<int N>
__device__ __forceinline__ void cp_wait() {
    asm volatile("cp.async.wait_group %0;\n" :: "n"(N));
}
__device__ __forceinline__ uint32_t ldu(const float* p) {
    return __float_as_uint(*p);
}
__device__ __forceinline__ uint32_t smem_u32(const void* p) {
    return (uint32_t)__cvta_generic_to_shared(p);
}

// =============================================================================
// fp32 -> tf32-rounded fp32 copies (weights only, 4 regions)
// =============================================================================
struct ConvArgs {
    const float* src[4];
    float* dst[4];
    int n4;
};
__global__ void __launch_bounds__(256) conv_kernel(ConvArgs a)
{
    int rg = blockIdx.y;
    const float4* s = reinterpret_cast<const float4*>(a.src[rg]);
    float4* d = reinterpret_cast<float4*>(a.dst[rg]);
    for (int i = blockIdx.x * 256 + threadIdx.x; i < a.n4; i += gridDim.x * 256) {
        float4 v = s[i];
        v.x = f2tf_f(v.x); v.y = f2tf_f(v.y);
        v.z = f2tf_f(v.z); v.w = f2tf_f(v.w);
        d[i] = v;
    }
}

struct Proj3Args {
    const float* A[3];
    const float* B[3];
    float*       C[3];
};

// =============================================================================
// Big NT GEMM: C = A * B^T. B pre-rounded; A rounded post-ldmatrix iff CVT_A.
// 128x128 tile, 128 threads, warp tile 64x64, ldmatrix fragments, 3 CTAs/SM.
// PROJ3: z selects (A,B,C); z=1 (K) and z=2 (V) skip row-blocks whose
// sequence rows are never read by the vl-limited flash kernel.
// =============================================================================
template<bool PROJ3, bool CVT_A>
__global__ void __launch_bounds__(128, 3)
gemm_big(Proj3Args args, int M, int N, int K, const int* __restrict__ vlp)
{
    constexpr int BM = 128, BN = 128, BK = 32, T = 128;
    constexpr int ASZ = BM * (BK + 4);
    constexpr int BSZ = BN * (BK + 4);
    constexpr int ABYTES = ASZ * 4;
    constexpr int BBYTES = BSZ * 4;

    int z = PROJ3 ? blockIdx.z : 0;
    int m0 = blockIdx.y * BM, n0 = blockIdx.x * BN;

    if (PROJ3 && z > 0) {
        // K/V projection: rows s >= ceil64(vl[b]) are never read downstream.
        int b = m0 >> 10;                       // BM=128 block is within one batch
        int vlc = (vlp[b] + 63) & ~63;
        if ((m0 & 1023) >= vlc) return;
    }

    extern __shared__ float dynsmem[];
    float (*As)[BM][BK + 4] = reinterpret_cast<float(*)[BM][BK + 4]>(dynsmem);
    float (*Bs)[BN][BK + 4] = reinterpret_cast<float(*)[BN][BK + 4]>(dynsmem + 2 * ASZ);

    const float* A = args.A[z];
    const float* B = args.B[z];
    float*       C = args.C[z];

    int tid = threadIdx.x;
    int lane = tid & 31, warp = tid >> 5;
    int gid = lane >> 2, tig = lane & 3;
    int wm0 = (warp >> 1) * 64;
    int wn0 = (warp & 1) * 64;

    int Lm = lane >> 3, Lr = lane & 7;
    int a_row = ((Lm & 1) ? 8 : 0) + Lr;
    int a_col = (Lm & 2) ? 4 : 0;
    int b_row = ((Lm & 2) ? 8 : 0) + Lr;
    int b_col = (Lm & 1) ? 4 : 0;

    uint32_t sA = smem_u32(&As[0][0][0]);
    uint32_t sB = smem_u32(&Bs[0][0][0]);
    uint32_t aBase[4], bBase[4];
    #pragma unroll
    for (int mt = 0; mt < 4; mt++)
        aBase[mt] = sA + ((wm0 + mt * 16 + a_row) * (BK + 4) + a_col) * 4;
    #pragma unroll
    for (int np = 0; np < 4; np++)
        bBase[np] = sB + ((wn0 + np * 16 + b_row) * (BK + 4) + b_col) * 4;

    auto load_tiles = [&](int buf, int k0) {
        #pragma unroll
        for (int it = 0; it < 8; it++) {
            int idx = tid + it * T;
            int row = idx >> 3, kq = (idx & 7) << 2;
            cp16(&As[buf][row][kq], &A[(size_t)(m0 + row) * K + k0 + kq]);
        }
        #pragma unroll
        for (int it = 0; it < 8; it++) {
            int idx = tid + it * T;
            int row = idx >> 3, kq = (idx & 7) << 2;
            cp16(&Bs[buf][row][kq], &B[(size_t)(n0 + row) * K + k0 + kq]);
        }
        cp_commit();
    };

    float acc[4][8][4];
    #pragma unroll
    for (int i = 0; i < 4; i++)
        #pragma unroll
        for (int j = 0; j < 8; j++)
            #pragma unroll
            for (int l = 0; l < 4; l++) acc[i][j][l] = 0.f;

    const int KT = K / BK;
    load_tiles(0, 0);

    for (int kt = 0; kt < KT; kt++) {
        int buf = kt & 1;
        if (kt + 1 < KT) { load_tiles(buf ^ 1, (kt + 1) * BK); cp_wait<1>(); }
        else             { cp_wait<0>(); }
        __syncthreads();

        uint32_t aOff = buf * ABYTES;
        uint32_t bOff = buf * BBYTES;
        #pragma unroll
        for (int kc = 0; kc < BK / 8; kc++) {
            uint32_t kb4 = kc * 32;
            uint32_t af[4][4];
            #pragma unroll
            for (int mt = 0; mt < 4; mt++) {
                ldsm4(af[mt][0], af[mt][1], af[mt][2], af[mt][3],
                      aBase[mt] + aOff + kb4);
                if (CVT_A) {
                    af[mt][0] = f2tf_u(af[mt][0]);
                    af[mt][1] = f2tf_u(af[mt][1]);
                    af[mt][2] = f2tf_u(af[mt][2]);
                    af[mt][3] = f2tf_u(af[mt][3]);
                }
            }
            uint32_t bf[8][2];
            #pragma unroll
            for (int np = 0; np < 4; np++)
                ldsm4(bf[2*np][0], bf[2*np][1], bf[2*np+1][0], bf[2*np+1][1],
                      bBase[np] + bOff + kb4);
            #pragma unroll
            for (int mt = 0; mt < 4; mt++)
                #pragma unroll
                for (int nt = 0; nt < 8; nt++)
                    mma8(acc[mt][nt], af[mt][0], af[mt][1], af[mt][2], af[mt][3],
                         bf[nt][0], bf[nt][1]);
        }
        __syncthreads();
    }

    #pragma unroll
    for (int mt = 0; mt < 4; mt++) {
        #pragma unroll
        for (int nt = 0; nt < 8; nt++) {
            int r0 = m0 + wm0 + mt * 16 + gid;
            int c0 = n0 + wn0 + nt * 8 + 2 * tig;
            if (PROJ3) {
                float2 t0 = make_float2(f2tf_f(acc[mt][nt][0]), f2tf_f(acc[mt][nt][1]));
                float2 t1 = make_float2(f2tf_f(acc[mt][nt][2]), f2tf_f(acc[mt][nt][3]));
                int b = r0 >> 10, s = r0 & 1023, h = c0 >> 6, d = c0 & 63;
                *reinterpret_cast<float2*>(
                    &C[(size_t)((b * NH + h) * SEQ + s) * HD + d]) = t0;
                int b2 = (r0 + 8) >> 10, s2 = (r0 + 8) & 1023;
                *reinterpret_cast<float2*>(
                    &C[(size_t)((b2 * NH + h) * SEQ + s2) * HD + d]) = t1;
            } else {
                float2 t0 = make_float2(acc[mt][nt][0], acc[mt][nt][1]);
                float2 t1 = make_float2(acc[mt][nt][2], acc[mt][nt][3]);
                *reinterpret_cast<float2*>(&C[(size_t)r0 * N + c0]) = t0;
                *reinterpret_cast<float2*>(&C[(size_t)(r0 + 8) * N + c0]) = t1;
            }
        }
    }
}

// =============================================================================
// Fused flash attention (shuffle-P, single-buffered V, ldmatrix K fragments).
// =============================================================================
__global__ void __launch_bounds__(128, 3)
flash_kernel(const int* __restrict__ valid_lens,
             const float* __restrict__ Ek, const float* __restrict__ Ev)
{
    constexpr int KS = 68;
    constexpr int TILE = 64 * KS;
    constexpr int TILEB = TILE * 4;

    extern __shared__ float sm[];
    float* Ks = sm;                 // [2][64][68]
    float* Vs = Ks + 2 * TILE;      // [64][68]  (also Ek/Ev staging)
    float* SQ = Vs + TILE;          // [64][33]
    float* SMID = SQ + 64 * NREL;   // [64][33]
    float* MR = SMID + 64 * NREL;   // [64]
    float* IL = MR + 64;            // [64]

    const int q0 = blockIdx.x * 64;
    const int bh = blockIdx.y;
    const int vl  = valid_lens[bh >> 4];
    const int vlc = (vl + 63) & ~63;

    const int tid = threadIdx.x;
    const int lane = tid & 31, warp = tid >> 5;
    const int gid = lane >> 2, tig = lane & 3;
    const int wq = warp * 16;

    int Lm = lane >> 3, Lr = lane & 7;
    int b_row = ((Lm & 2) ? 8 : 0) + Lr;
    int b_col = (Lm & 1) ? 4 : 0;
    uint32_t sK = smem_u32(Ks);
    uint32_t kBase[4];
    #pragma unroll
    for (int np = 0; np < 4; np++)
        kBase[np] = sK + ((np * 16 + b_row) * KS + b_col) * 4;

    auto loadK = [&](int buf, int k0) {
        const float* Kg = g_K + ((size_t)bh * SEQ + k0) * HD;
        #pragma unroll
        for (int it = 0; it < 8; it++) {
            int idx = tid + it * 128;
            int row = idx >> 4, c4 = (idx & 15) << 2;
            cp16(&Ks[buf * TILE + row * KS + c4], Kg + row * HD + c4);
        }
        cp_commit();
    };
    auto loadV = [&](int k0) {
        const float* Vg = g_V + ((size_t)bh * SEQ + k0) * HD;
        #pragma unroll
        for (int it = 0; it < 8; it++) {
            int idx = tid + it * 128;
            int row = idx >> 4, c4 = (idx & 15) << 2;
            cp16(&Vs[row * KS + c4], Vg + row * HD + c4);
        }
        cp_commit();
    };

    loadK(0, 0);

    for (int i = tid; i < NREL * 16; i += 128) {
        int row = i >> 4, c = i & 15;
        *reinterpret_cast<float4*>(&Vs[row * KS + 4 * c]) =
            reinterpret_cast<const float4*>(Ek)[i];
    }

    uint32_t qa[8][4];
    {
        const float* Qg = g_Q + ((size_t)bh * SEQ + q0 + wq) * HD;
        #pragma unroll
        for (int kc = 0; kc < 8; kc++) {
            qa[kc][0] = ldu(&Qg[(size_t)gid       * HD + kc * 8 + tig]);
            qa[kc][1] = ldu(&Qg[(size_t)(gid + 8) * HD + kc * 8 + tig]);
            qa[kc][2] = ldu(&Qg[(size_t)gid       * HD + kc * 8 + tig + 4]);
            qa[kc][3] = ldu(&Qg[(size_t)(gid + 8) * HD + kc * 8 + tig + 4]);
        }
    }
    __syncthreads();

    {
        float sq[5][4];
        #pragma unroll
        for (int nt = 0; nt < 5; nt++)
            #pragma unroll
            for (int e = 0; e < 4; e++) sq[nt][e] = 0.f;
        #pragma unroll
        for (int kc = 0; kc < 8; kc++) {
            #pragma unroll
            for (int nt = 0; nt < 5; nt++) {
                uint32_t b0 = f2tf(Vs[(nt * 8 + gid) * KS + kc * 8 + tig]);
                uint32_t b1 = f2tf(Vs[(nt * 8 + gid) * KS + kc * 8 + tig + 4]);
                mma8(sq[nt], qa[kc][0], qa[kc][1], qa[kc][2], qa[kc][3], b0, b1);
            }
        }
        #pragma unroll
        for (int nt = 0; nt < 5; nt++) {
            #pragma unroll
            for (int e = 0; e < 4; e++) {
                int col = nt * 8 + 2 * tig + (e & 1);
                int row = wq + gid + ((e < 2) ? 0 : 8);
                if (col < NREL) SQ[row * NREL + col] = sq[nt][e];
            }
        }
    }
    for (int i = tid; i < 64 * NREL; i += 128) SMID[i] = NEGV;
    __syncthreads();

    const int qrow0 = q0 + wq + gid;
    const int qrow1 = qrow0 + 8;

    float oa[8][4];
    #pragma unroll
    for (int nt = 0; nt < 8; nt++)
        #pragma unroll
        for (int j = 0; j < 4; j++) oa[nt][j] = 0.f;

    float m0 = -1e30f, m1 = -1e30f;
    float l0 = 0.f, l1 = 0.f;
    float eL0 = 0.f, eL1 = 0.f, eH0 = 0.f, eH1 = 0.f;

    const int KT = vlc / 64;
    for (int t = 0; t < KT; t++) {
        int buf = t & 1;
        int k0 = t * 64;
        loadV(k0);
        if (t + 1 < KT) { loadK(buf ^ 1, k0 + 64); cp_wait<2>(); }
        else            { cp_wait<1>(); }
        __syncthreads();

        float sa[8][4];
        #pragma unroll
        for (int nt = 0; nt < 8; nt++)
            #pragma unroll
            for (int j = 0; j < 4; j++) sa[nt][j] = 0.f;

        uint32_t kOff = buf * TILEB;
        #pragma unroll
        for (int kc = 0; kc < 8; kc++) {
            uint32_t bf[8][2];
            #pragma unroll
            for (int np = 0; np < 4; np++)
                ldsm4(bf[2*np][0], bf[2*np][1], bf[2*np+1][0], bf[2*np+1][1],
                      kBase[np] + kOff + kc * 32);
            #pragma unroll
            for (int nt = 0; nt < 8; nt++)
                mma8(sa[nt], qa[kc][0], qa[kc][1], qa[kc][2], qa[kc][3],
                     bf[nt][0], bf[nt][1]);
        }

        float tm0 = -1e30f, tm1 = -1e30f;
        #pragma unroll
        for (int nt = 0; nt < 8; nt++) {
            int kc0 = k0 + nt * 8 + 2 * tig;
            #pragma unroll
            for (int e = 0; e < 4; e++) {
                int kcol = kc0 + (e & 1);
                int qrow = (e < 2) ? qrow0 : qrow1;
                int rloc = wq + gid + ((e < 2) ? 0 : 8);
                int d = kcol - qrow;
                int bidx = min(16, max(-16, d)) + 16;
                float s = (sa[nt][e] + SQ[rloc * NREL + bidx]) * SCALE;
                if (kcol >= vl) s = NEGV;
                sa[nt][e] = s;
                if (d > -16 && d < 16) SMID[rloc * NREL + bidx] = s;
                if (e < 2) tm0 = fmaxf(tm0, s); else tm1 = fmaxf(tm1, s);
            }
        }
        tm0 = fmaxf(tm0, __shfl_xor_sync(0xffffffffu, tm0, 1));
        tm0 = fmaxf(tm0, __shfl_xor_sync(0xffffffffu, tm0, 2));
        tm1 = fmaxf(tm1, __shfl_xor_sync(0xffffffffu, tm1, 1));
        tm1 = fmaxf(tm1, __shfl_xor_sync(0xffffffffu, tm1, 2));

        float mn0 = fmaxf(m0, tm0), mn1 = fmaxf(m1, tm1);
        float a0 = exp2f(m0 - mn0), a1 = exp2f(m1 - mn1);
        m0 = mn0; m1 = mn1;

        float ps0 = 0.f, ps1 = 0.f, tl0 = 0.f, tl1 = 0.f, th0 = 0.f, th1 = 0.f;
        #pragma unroll
        for (int nt = 0; nt < 8; nt++) {
            int kc0 = k0 + nt * 8 + 2 * tig;
            #pragma unroll
            for (int e = 0; e < 4; e++) {
                int kcol = kc0 + (e & 1);
                float p = exp2f(sa[nt][e] - ((e < 2) ? mn0 : mn1));
                sa[nt][e] = p;
                int d = kcol - ((e < 2) ? qrow0 : qrow1);
                if (e < 2) {
                    ps0 += p;
                    if (d <= -16) tl0 += p; else if (d >= 16) th0 += p;
                } else {
                    ps1 += p;
                    if (d <= -16) tl1 += p; else if (d >= 16) th1 += p;
                }
            }
        }
        ps0 += __shfl_xor_sync(0xffffffffu, ps0, 1); ps0 += __shfl_xor_sync(0xffffffffu, ps0, 2);
        ps1 += __shfl_xor_sync(0xffffffffu, ps1, 1); ps1 += __shfl_xor_sync(0xffffffffu, ps1, 2);
        tl0 += __shfl_xor_sync(0xffffffffu, tl0, 1); tl0 += __shfl_xor_sync(0xffffffffu, tl0, 2);
        tl1 += __shfl_xor_sync(0xffffffffu, tl1, 1); tl1 += __shfl_xor_sync(0xffffffffu, tl1, 2);
        th0 += __shfl_xor_sync(0xffffffffu, th0, 1); th0 += __shfl_xor_sync(0xffffffffu, th0, 2);
        th1 += __shfl_xor_sync(0xffffffffu, th1, 1); th1 += __shfl_xor_sync(0xffffffffu, th1, 2);

        l0 = l0 * a0 + ps0;  l1 = l1 * a1 + ps1;
        eL0 = eL0 * a0 + tl0; eL1 = eL1 * a1 + tl1;
        eH0 = eH0 * a0 + th0; eH1 = eH1 * a1 + th1;

        #pragma unroll
        for (int nt = 0; nt < 8; nt++) {
            oa[nt][0] *= a0; oa[nt][1] *= a0;
            oa[nt][2] *= a1; oa[nt][3] *= a1;
        }

        if (t + 1 < KT) cp_wait<1>(); else cp_wait<0>();
        __syncthreads();    // V(t) visible

        const int L0 = (gid << 2) + (tig >> 1);
        const int L1 = L0 + 2;
        const bool odd = (tig & 1) != 0;
        #pragma unroll
        for (int kc = 0; kc < 8; kc++) {
            float a0e = __shfl_sync(0xffffffffu, sa[kc][0], L0);
            float a0o = __shfl_sync(0xffffffffu, sa[kc][1], L0);
            float a1e = __shfl_sync(0xffffffffu, sa[kc][2], L0);
            float a1o = __shfl_sync(0xffffffffu, sa[kc][3], L0);
            float a2e = __shfl_sync(0xffffffffu, sa[kc][0], L1);
            float a2o = __shfl_sync(0xffffffffu, sa[kc][1], L1);
            float a3e = __shfl_sync(0xffffffffu, sa[kc][2], L1);
            float a3o = __shfl_sync(0xffffffffu, sa[kc][3], L1);
            uint32_t p0 = f2tf(odd ? a0o : a0e);
            uint32_t p1 = f2tf(odd ? a1o : a1e);
            uint32_t p2 = f2tf(odd ? a2o : a2e);
            uint32_t p3 = f2tf(odd ? a3o : a3e);
            #pragma unroll
            for (int nt = 0; nt < 8; nt++) {
                uint32_t b0 = ldu(&Vs[(kc * 8 + tig)     * KS + nt * 8 + gid]);
                uint32_t b1 = ldu(&Vs[(kc * 8 + tig + 4) * KS + nt * 8 + gid]);
                mma8(oa[nt], p0, p1, p2, p3, b0, b1);
            }
        }
        __syncthreads();
    }

    // ---- epilogue ----
    const int b = bh >> 4, h = bh & 15;
    float il0 = 1.f / l0, il1 = 1.f / l1;

    if (tig == 0) {
        MR[wq + gid] = m0;     IL[wq + gid] = il0;
        MR[wq + gid + 8] = m1; IL[wq + gid + 8] = il1;
        SQ[(wq + gid) * NREL + 0]      = eL0 * il0;
        SQ[(wq + gid) * NREL + 32]     = eH0 * il0;
        SQ[(wq + gid + 8) * NREL + 0]  = eL1 * il1;
        SQ[(wq + gid + 8) * NREL + 32] = eH1 * il1;
    }
    for (int i = tid; i < NREL * 16; i += 128) {
        int row = i >> 4, c = i & 15;
        *reinterpret_cast<float4*>(&Vs[row * KS + 4 * c]) =
            reinterpret_cast<const float4*>(Ev)[i];
    }
    __syncthreads();

    for (int i = tid; i < 64 * 31; i += 128) {
        int row = i / 31, r = i % 31 + 1;
        SQ[row * NREL + r] = exp2f(SMID[row * NREL + r] - MR[row]) * IL[row];
    }
    __syncthreads();

    #pragma unroll
    for (int nt = 0; nt < 8; nt++) {
        oa[nt][0] *= il0; oa[nt][1] *= il0;
        oa[nt][2] *= il1; oa[nt][3] *= il1;
    }
    for (int r = 0; r < NREL; r++) {
        float pr0 = SQ[(wq + gid) * NREL + r];
        float pr1 = SQ[(wq + gid + 8) * NREL + r];
        #pragma unroll
        for (int nt = 0; nt < 8; nt++) {
            float2 ev = *reinterpret_cast<const float2*>(&Vs[r * KS + nt * 8 + 2 * tig]);
            oa[nt][0] += pr0 * ev.x; oa[nt][1] += pr0 * ev.y;
            oa[nt][2] += pr1 * ev.x; oa[nt][3] += pr1 * ev.y;
        }
    }
    #pragma unroll
    for (int nt = 0; nt < 8; nt++) {
        int col = h * HD + nt * 8 + 2 * tig;
        *reinterpret_cast<float2*>(&g_ctx[(size_t)(b * SEQ + qrow0) * DM + col]) =
            make_float2(f2tf_f(oa[nt][0]), f2tf_f(oa[nt][1]));
        *reinterpret_cast<float2*>(&g_ctx[(size_t)(b * SEQ + qrow1) * DM + col]) =
            make_float2(f2tf_f(oa[nt][2]), f2tf_f(oa[nt][3]));
    }
}

// ---------------- launch ------------------------------------------------------
extern "C" void kernel_launch(void* const* d_in, const int* in_sizes, int n_in,
                              void* d_out, int out_size)
{
    const float* queries = (const float*)d_in[0];
    const float* keys    = (const float*)d_in[1];
    const float* values  = (const float*)d_in[2];
    const int*   valid   = (const int*)  d_in[3];
    const float* Wq      = (const float*)d_in[4];
    const float* Wk      = (const float*)d_in[5];
    const float* Wv      = (const float*)d_in[6];
    const float* Wo      = (const float*)d_in[7];
    const float* Ek      = (const float*)d_in[8];
    const float* Ev      = (const float*)d_in[9];
    float* out = (float*)d_out;

    float *Qp, *Kp, *Vp, *Cp, *rw;
    cudaGetSymbolAddress((void**)&Qp, g_Q);
    cudaGetSymbolAddress((void**)&Kp, g_K);
    cudaGetSymbolAddress((void**)&Vp, g_V);
    cudaGetSymbolAddress((void**)&Cp, g_ctx);
    cudaGetSymbolAddress((void**)&rw, g_rw);

    const int M = BATCH * SEQ;          // 4096
    const size_t WN = (size_t)DM * DM;  // 1M

    const int smBig   = 2 * (128 * 36 + 128 * 36) * sizeof(float);   // 73728
    const int smFlash = (2 * 64 * 68 + 64 * 68
                         + 64 * NREL + 64 * NREL + 128) * sizeof(float); // 69632

    cudaFuncSetAttribute(gemm_big<true, true>,
        cudaFuncAttributeMaxDynamicSharedMemorySize, smBig);
    cudaFuncSetAttribute(gemm_big<false, false>,
        cudaFuncAttributeMaxDynamicSharedMemorySize, smBig);
    cudaFuncSetAttribute(flash_kernel,
        cudaFuncAttributeMaxDynamicSharedMemorySize, smFlash);

    // 1) pre-round WEIGHTS only (inputs rounded in-register in proj3)
    ConvArgs ca;
    ca.src[0] = Wq; ca.src[1] = Wk; ca.src[2] = Wv; ca.src[3] = Wo;
    for (int i = 0; i < 4; i++) ca.dst[i] = rw + i * WN;
    ca.n4 = (int)(WN / 4);
    conv_kernel<<<dim3(128, 4), 256>>>(ca);

    // 2) Q/K/V projections; K/V row-blocks beyond ceil64(vl) skipped
    Proj3Args pa;
    pa.A[0] = queries;      pa.A[1] = keys;         pa.A[2] = values;
    pa.B[0] = rw;           pa.B[1] = rw + WN;      pa.B[2] = rw + 2 * WN;
    pa.C[0] = Qp;           pa.C[1] = Kp;           pa.C[2] = Vp;
    gemm_big<true, true><<<dim3(DM / 128, M / 128, 3), 128, smBig>>>(
        pa, M, DM, DM, valid);

    // 3) fused attention
    flash_kernel<<<dim3(SEQ / 64, BH), 128, smFlash>>>(valid, Ek, Ev);

    // 4) out = ctx @ Wo^T (ctx pre-rounded by flash epilogue -> cvt-free)
    Proj3Args po;
    po.A[0] = Cp; po.B[0] = rw + 3 * WN; po.C[0] = out;
    po.A[1] = po.A[2] = Cp; po.B[1] = po.B[2] = rw; po.C[1] = po.C[2] = out;
    gemm_big<false, false><<<dim3(DM / 128, M / 128, 1), 128, smBig>>>(
        po, M, DM, DM, nullptr);
}

// round 14
// speedup vs baseline: 1.3484x; 1.0264x over previous
#include <cuda_runtime.h>
#include <math.h>
#include <stdint.h>

#define BATCH 4
#define SEQ   1024
#define DM    1024
#define NH    16
#define HD    64
#define BH    (BATCH*NH)   // 64
#define NREL  33
#define NEGV  (-1e6f)
#define SCALE 0.1803368801111243f   // (1/sqrt(64)) * log2(e)

// ---------------- scratch (device globals: allocation is forbidden) ----------
__device__ float g_Q[BH*SEQ*HD];                 // [bh][s][d]  (tf32-rounded)
__device__ float g_K[BH*SEQ*HD];                 // [bh][s][d]
__device__ float g_V[BH*SEQ*HD];                 // [bh][d][s]  TRANSPOSED
__device__ float g_ctx[BATCH*SEQ*DM];            // merged-head ctx (tf32-rounded)
__device__ float g_rw [4u*1024*1024];            // pre-rounded Wq,Wk,Wv,Wo

// ---------------- helpers ----------------------------------------------------
__device__ __forceinline__ uint32_t f2tf(float f) {
    uint32_t u;
    asm("cvt.rna.tf32.f32 %0, %1;" : "=r"(u) : "f"(f));
    return u;
}
__device__ __forceinline__ float f2tf_f(float f) {
    return __uint_as_float(f2tf(f));
}
__device__ __forceinline__ uint32_t f2tf_u(uint32_t raw) {
    uint32_t u;
    asm("cvt.rna.tf32.f32 %0, %1;" : "=r"(u) : "f"(__uint_as_float(raw)));
    return u;
}
__device__ __forceinline__ void mma8(float* c,
    uint32_t a0, uint32_t a1, uint32_t a2, uint32_t a3,
    uint32_t b0, uint32_t b1)
{
    asm volatile(
        "mma.sync.aligned.m16n8k8.row.col.f32.tf32.tf32.f32 "
        "{%0,%1,%2,%3}, {%4,%5,%6,%7}, {%8,%9}, {%0,%1,%2,%3};"
        : "+f"(c[0]), "+f"(c[1]), "+f"(c[2]), "+f"(c[3])
        : "r"(a0), "r"(a1), "r"(a2), "r"(a3), "r"(b0), "r"(b1));
}
__device__ __forceinline__ void ldsm4(uint32_t& r0, uint32_t& r1,
                                      uint32_t& r2, uint32_t& r3, uint32_t addr)
{
    asm volatile("ldmatrix.sync.aligned.m8n8.x4.shared.b16 {%0,%1,%2,%3}, [%4];"
        : "=r"(r0), "=r"(r1), "=r"(r2), "=r"(r3) : "r"(addr));
}
__device__ __forceinline__ void cp16(void* smem_dst, const void* gmem_src) {
    uint32_t s = (uint32_t)__cvta_generic_to_shared(smem_dst);
    asm volatile("cp.async.cg.shared.global [%0], [%1], 16;\n"
                 :: "r"(s), "l"(gmem_src));
}
__device__ __forceinline__ void cp_commit() {
    asm volatile("cp.async.commit_group;\n");
}
template<int N>
__device__ __forceinline__ void cp_wait() {
    asm volatile("cp.async.wait_group %0;\n" :: "n"(N));
}
__device__ __forceinline__ uint32_t ldu(const float* p) {
    return __float_as_uint(*p);
}
__device__ __forceinline__ uint32_t smem_u32(const void* p) {
    return (uint32_t)__cvta_generic_to_shared(p);
}

// =============================================================================
// fp32 -> tf32-rounded fp32 copies (weights only)
// =============================================================================
struct ConvArgs {
    const float* src[4];
    float* dst[4];
    int n4;
};
__global__ void __launch_bounds__(256) conv_kernel(ConvArgs a)
{
    int rg = blockIdx.y;
    const float4* s = reinterpret_cast<const float4*>(a.src[rg]);
    float4* d = reinterpret_cast<float4*>(a.dst[rg]);
    for (int i = blockIdx.x * 256 + threadIdx.x; i < a.n4; i += gridDim.x * 256) {
        float4 v = s[i];
        v.x = f2tf_f(v.x); v.y = f2tf_f(v.y);
        v.z = f2tf_f(v.z); v.w = f2tf_f(v.w);
        d[i] = v;
    }
}

struct Proj3Args {
    const float* A[3];
    const float* B[3];
    float*       C[3];
};

// =============================================================================
// Big NT GEMM. PROJ3: z=1,2 (K,V) skip vl-dead row blocks; z=2 (V) stores
// TRANSPOSED [bh][d][s]. CVT_A: round A fragments post-ldmatrix.
// =============================================================================
template<bool PROJ3, bool CVT_A>
__global__ void __launch_bounds__(128, 3)
gemm_big(Proj3Args args, int M, int N, int K, const int* __restrict__ vlp)
{
    constexpr int BM = 128, BN = 128, BK = 32, T = 128;
    constexpr int ASZ = BM * (BK + 4);
    constexpr int ABYTES = ASZ * 4;
    constexpr int BBYTES = BN * (BK + 4) * 4;

    int z = PROJ3 ? blockIdx.z : 0;
    int m0 = blockIdx.y * BM, n0 = blockIdx.x * BN;

    if (PROJ3 && z > 0) {
        int b = m0 >> 10;
        int vlc = (vlp[b] + 63) & ~63;
        if ((m0 & 1023) >= vlc) return;
    }

    extern __shared__ float dynsmem[];
    float (*As)[BM][BK + 4] = reinterpret_cast<float(*)[BM][BK + 4]>(dynsmem);
    float (*Bs)[BN][BK + 4] = reinterpret_cast<float(*)[BN][BK + 4]>(dynsmem + 2 * ASZ);

    const float* A = args.A[z];
    const float* B = args.B[z];
    float*       C = args.C[z];

    int tid = threadIdx.x;
    int lane = tid & 31, warp = tid >> 5;
    int gid = lane >> 2, tig = lane & 3;
    int wm0 = (warp >> 1) * 64;
    int wn0 = (warp & 1) * 64;

    int Lm = lane >> 3, Lr = lane & 7;
    int a_row = ((Lm & 1) ? 8 : 0) + Lr;
    int a_col = (Lm & 2) ? 4 : 0;
    int b_row = ((Lm & 2) ? 8 : 0) + Lr;
    int b_col = (Lm & 1) ? 4 : 0;

    uint32_t sA = smem_u32(&As[0][0][0]);
    uint32_t sB = smem_u32(&Bs[0][0][0]);
    uint32_t aBase[4], bBase[4];
    #pragma unroll
    for (int mt = 0; mt < 4; mt++)
        aBase[mt] = sA + ((wm0 + mt * 16 + a_row) * (BK + 4) + a_col) * 4;
    #pragma unroll
    for (int np = 0; np < 4; np++)
        bBase[np] = sB + ((wn0 + np * 16 + b_row) * (BK + 4) + b_col) * 4;

    auto load_tiles = [&](int buf, int k0) {
        #pragma unroll
        for (int it = 0; it < 8; it++) {
            int idx = tid + it * T;
            int row = idx >> 3, kq = (idx & 7) << 2;
            cp16(&As[buf][row][kq], &A[(size_t)(m0 + row) * K + k0 + kq]);
        }
        #pragma unroll
        for (int it = 0; it < 8; it++) {
            int idx = tid + it * T;
            int row = idx >> 3, kq = (idx & 7) << 2;
            cp16(&Bs[buf][row][kq], &B[(size_t)(n0 + row) * K + k0 + kq]);
        }
        cp_commit();
    };

    float acc[4][8][4];
    #pragma unroll
    for (int i = 0; i < 4; i++)
        #pragma unroll
        for (int j = 0; j < 8; j++)
            #pragma unroll
            for (int l = 0; l < 4; l++) acc[i][j][l] = 0.f;

    const int KT = K / BK;
    load_tiles(0, 0);

    for (int kt = 0; kt < KT; kt++) {
        int buf = kt & 1;
        if (kt + 1 < KT) { load_tiles(buf ^ 1, (kt + 1) * BK); cp_wait<1>(); }
        else             { cp_wait<0>(); }
        __syncthreads();

        uint32_t aOff = buf * ABYTES;
        uint32_t bOff = buf * BBYTES;
        #pragma unroll
        for (int kc = 0; kc < BK / 8; kc++) {
            uint32_t kb4 = kc * 32;
            uint32_t af[4][4];
            #pragma unroll
            for (int mt = 0; mt < 4; mt++) {
                ldsm4(af[mt][0], af[mt][1], af[mt][2], af[mt][3],
                      aBase[mt] + aOff + kb4);
                if (CVT_A) {
                    af[mt][0] = f2tf_u(af[mt][0]);
                    af[mt][1] = f2tf_u(af[mt][1]);
                    af[mt][2] = f2tf_u(af[mt][2]);
                    af[mt][3] = f2tf_u(af[mt][3]);
                }
            }
            uint32_t bf[8][2];
            #pragma unroll
            for (int np = 0; np < 4; np++)
                ldsm4(bf[2*np][0], bf[2*np][1], bf[2*np+1][0], bf[2*np+1][1],
                      bBase[np] + bOff + kb4);
            #pragma unroll
            for (int mt = 0; mt < 4; mt++)
                #pragma unroll
                for (int nt = 0; nt < 8; nt++)
                    mma8(acc[mt][nt], af[mt][0], af[mt][1], af[mt][2], af[mt][3],
                         bf[nt][0], bf[nt][1]);
        }
        __syncthreads();
    }

    #pragma unroll
    for (int mt = 0; mt < 4; mt++) {
        #pragma unroll
        for (int nt = 0; nt < 8; nt++) {
            int r0 = m0 + wm0 + mt * 16 + gid;
            int c0 = n0 + wn0 + nt * 8 + 2 * tig;
            if (PROJ3) {
                int b = r0 >> 10, s = r0 & 1023, h = c0 >> 6, d = c0 & 63;
                float v0 = f2tf_f(acc[mt][nt][0]), v1 = f2tf_f(acc[mt][nt][1]);
                float v2 = f2tf_f(acc[mt][nt][2]), v3 = f2tf_f(acc[mt][nt][3]);
                if (z == 2) {
                    // V: transposed store [bh][d][s] (s, s+8 in same batch)
                    float* p = C + ((size_t)((b * NH + h) * HD + d)) * SEQ + s;
                    p[0] = v0;  p[SEQ] = v1;
                    p[8] = v2;  p[SEQ + 8] = v3;
                } else {
                    *reinterpret_cast<float2*>(
                        &C[(size_t)((b * NH + h) * SEQ + s) * HD + d]) =
                        make_float2(v0, v1);
                    *reinterpret_cast<float2*>(
                        &C[(size_t)((b * NH + h) * SEQ + s + 8) * HD + d]) =
                        make_float2(v2, v3);
                }
            } else {
                *reinterpret_cast<float2*>(&C[(size_t)r0 * N + c0]) =
                    make_float2(acc[mt][nt][0], acc[mt][nt][1]);
                *reinterpret_cast<float2*>(&C[(size_t)(r0 + 8) * N + c0]) =
                    make_float2(acc[mt][nt][2], acc[mt][nt][3]);
            }
        }
    }
}

// =============================================================================
// Fused flash attention: shuffle-P, ldmatrix K AND V (V^T layout),
// band-classified rel-pos softmax (bit-identical to the full path).
// =============================================================================
__global__ void __launch_bounds__(128, 3)
flash_kernel(const int* __restrict__ valid_lens,
             const float* __restrict__ Ek, const float* __restrict__ Ev)
{
    constexpr int KS = 68;
    constexpr int TILE = 64 * KS;
    constexpr int TILEB = TILE * 4;

    extern __shared__ float sm[];
    float* Ks = sm;                 // [2][64][68]  K rows [k][d]
    float* Vs = Ks + 2 * TILE;      // [64][68]     V^T rows [d][k]; Ek/Ev staging
    float* SQ = Vs + TILE;          // [64][33]
    float* SMID = SQ + 64 * NREL;   // [64][33]
    float* MR = SMID + 64 * NREL;   // [64]
    float* IL = MR + 64;            // [64]

    const int q0 = blockIdx.x * 64;
    const int bh = blockIdx.y;
    const int vl  = valid_lens[bh >> 4];
    const int vlc = (vl + 63) & ~63;

    const int tid = threadIdx.x;
    const int lane = tid & 31, warp = tid >> 5;
    const int gid = lane >> 2, tig = lane & 3;
    const int wq = warp * 16;

    int Lm = lane >> 3, Lr = lane & 7;
    int b_row = ((Lm & 2) ? 8 : 0) + Lr;
    int b_col = (Lm & 1) ? 4 : 0;
    uint32_t sK = smem_u32(Ks);
    uint32_t sV = smem_u32(Vs);
    uint32_t kBase[4], vBase[4];
    #pragma unroll
    for (int np = 0; np < 4; np++) {
        kBase[np] = sK + ((np * 16 + b_row) * KS + b_col) * 4;
        vBase[np] = sV + ((np * 16 + b_row) * KS + b_col) * 4;
    }

    auto loadK = [&](int buf, int k0) {
        const float* Kg = g_K + ((size_t)bh * SEQ + k0) * HD;
        #pragma unroll
        for (int it = 0; it < 8; it++) {
            int idx = tid + it * 128;
            int row = idx >> 4, c4 = (idx & 15) << 2;
            cp16(&Ks[buf * TILE + row * KS + c4], Kg + row * HD + c4);
        }
        cp_commit();
    };
    auto loadV = [&](int k0) {
        // g_V is [bh][d][s]; tile rows d=0..63, cols s=k0..k0+63
        const float* Vg = g_V + (size_t)bh * HD * SEQ + k0;
        #pragma unroll
        for (int it = 0; it < 8; it++) {
            int idx = tid + it * 128;
            int row = idx >> 4, c4 = (idx & 15) << 2;
            cp16(&Vs[row * KS + c4], Vg + (size_t)row * SEQ + c4);
        }
        cp_commit();
    };

    loadK(0, 0);

    for (int i = tid; i < NREL * 16; i += 128) {
        int row = i >> 4, c = i & 15;
        *reinterpret_cast<float4*>(&Vs[row * KS + 4 * c]) =
            reinterpret_cast<const float4*>(Ek)[i];
    }

    uint32_t qa[8][4];
    {
        const float* Qg = g_Q + ((size_t)bh * SEQ + q0 + wq) * HD;
        #pragma unroll
        for (int kc = 0; kc < 8; kc++) {
            qa[kc][0] = ldu(&Qg[(size_t)gid       * HD + kc * 8 + tig]);
            qa[kc][1] = ldu(&Qg[(size_t)(gid + 8) * HD + kc * 8 + tig]);
            qa[kc][2] = ldu(&Qg[(size_t)gid       * HD + kc * 8 + tig + 4]);
            qa[kc][3] = ldu(&Qg[(size_t)(gid + 8) * HD + kc * 8 + tig + 4]);
        }
    }
    __syncthreads();

    {
        float sq[5][4];
        #pragma unroll
        for (int nt = 0; nt < 5; nt++)
            #pragma unroll
            for (int e = 0; e < 4; e++) sq[nt][e] = 0.f;
        #pragma unroll
        for (int kc = 0; kc < 8; kc++) {
            #pragma unroll
            for (int nt = 0; nt < 5; nt++) {
                uint32_t b0 = f2tf(Vs[(nt * 8 + gid) * KS + kc * 8 + tig]);
                uint32_t b1 = f2tf(Vs[(nt * 8 + gid) * KS + kc * 8 + tig + 4]);
                mma8(sq[nt], qa[kc][0], qa[kc][1], qa[kc][2], qa[kc][3], b0, b1);
            }
        }
        #pragma unroll
        for (int nt = 0; nt < 5; nt++) {
            #pragma unroll
            for (int e = 0; e < 4; e++) {
                int col = nt * 8 + 2 * tig + (e & 1);
                int row = wq + gid + ((e < 2) ? 0 : 8);
                if (col < NREL) SQ[row * NREL + col] = sq[nt][e];
            }
        }
    }
    for (int i = tid; i < 64 * NREL; i += 128) SMID[i] = NEGV;
    __syncthreads();

    const int qrow0 = q0 + wq + gid;
    const int qrow1 = qrow0 + 8;
    const int qlo = q0 + wq, qhi = qlo + 15;

    // per-row end-bucket bias values (registers; bit-identical to SQ lookups)
    const float sqL0 = SQ[(wq + gid) * NREL + 0];
    const float sqH0 = SQ[(wq + gid) * NREL + 32];
    const float sqL1 = SQ[(wq + gid + 8) * NREL + 0];
    const float sqH1 = SQ[(wq + gid + 8) * NREL + 32];

    float oa[8][4];
    #pragma unroll
    for (int nt = 0; nt < 8; nt++)
        #pragma unroll
        for (int j = 0; j < 4; j++) oa[nt][j] = 0.f;

    float m0 = -1e30f, m1 = -1e30f;
    float l0 = 0.f, l1 = 0.f;
    float eL0 = 0.f, eL1 = 0.f, eH0 = 0.f, eH1 = 0.f;

    const int KT = vlc / 64;
    for (int t = 0; t < KT; t++) {
        int buf = t & 1;
        int k0 = t * 64;
        const bool last = (t == KT - 1);
        loadV(k0);
        if (t + 1 < KT) { loadK(buf ^ 1, k0 + 64); cp_wait<2>(); }
        else            { cp_wait<1>(); }
        __syncthreads();

        // ---- S = Q K^T (ldmatrix K)
        float sa[8][4];
        #pragma unroll
        for (int nt = 0; nt < 8; nt++)
            #pragma unroll
            for (int j = 0; j < 4; j++) sa[nt][j] = 0.f;

        uint32_t kOff = buf * TILEB;
        #pragma unroll
        for (int kc = 0; kc < 8; kc++) {
            uint32_t bf[8][2];
            #pragma unroll
            for (int np = 0; np < 4; np++)
                ldsm4(bf[2*np][0], bf[2*np][1], bf[2*np+1][0], bf[2*np+1][1],
                      kBase[np] + kOff + kc * 32);
            #pragma unroll
            for (int nt = 0; nt < 8; nt++)
                mma8(sa[nt], qa[kc][0], qa[kc][1], qa[kc][2], qa[kc][3],
                     bf[nt][0], bf[nt][1]);
        }

        // ---- rel-pos add + scale + (last-tile) mask; band-classified
        float tm0 = -1e30f, tm1 = -1e30f;
        #pragma unroll
        for (int nt = 0; nt < 8; nt++) {
            int kg = k0 + nt * 8;
            if (kg >= qhi + 16) {                       // all d >= 16
                #pragma unroll
                for (int e = 0; e < 4; e++) {
                    float s = (sa[nt][e] + ((e < 2) ? sqH0 : sqH1)) * SCALE;
                    if (last) {
                        int kcol = kg + 2 * tig + (e & 1);
                        if (kcol >= vl) s = NEGV;
                    }
                    sa[nt][e] = s;
                    if (e < 2) tm0 = fmaxf(tm0, s); else tm1 = fmaxf(tm1, s);
                }
            } else if (kg + 7 <= qlo - 16) {            // all d <= -16
                #pragma unroll
                for (int e = 0; e < 4; e++) {
                    float s = (sa[nt][e] + ((e < 2) ? sqL0 : sqL1)) * SCALE;
                    if (last) {
                        int kcol = kg + 2 * tig + (e & 1);
                        if (kcol >= vl) s = NEGV;
                    }
                    sa[nt][e] = s;
                    if (e < 2) tm0 = fmaxf(tm0, s); else tm1 = fmaxf(tm1, s);
                }
            } else {                                    // straddle: full path
                int kc0 = kg + 2 * tig;
                #pragma unroll
                for (int e = 0; e < 4; e++) {
                    int kcol = kc0 + (e & 1);
                    int qrow = (e < 2) ? qrow0 : qrow1;
                    int rloc = wq + gid + ((e < 2) ? 0 : 8);
                    int d = kcol - qrow;
                    int bidx = min(16, max(-16, d)) + 16;
                    float s = (sa[nt][e] + SQ[rloc * NREL + bidx]) * SCALE;
                    if (last && kcol >= vl) s = NEGV;
                    sa[nt][e] = s;
                    if (d > -16 && d < 16) SMID[rloc * NREL + bidx] = s;
                    if (e < 2) tm0 = fmaxf(tm0, s); else tm1 = fmaxf(tm1, s);
                }
            }
        }
        tm0 = fmaxf(tm0, __shfl_xor_sync(0xffffffffu, tm0, 1));
        tm0 = fmaxf(tm0, __shfl_xor_sync(0xffffffffu, tm0, 2));
        tm1 = fmaxf(tm1, __shfl_xor_sync(0xffffffffu, tm1, 1));
        tm1 = fmaxf(tm1, __shfl_xor_sync(0xffffffffu, tm1, 2));

        float mn0 = fmaxf(m0, tm0), mn1 = fmaxf(m1, tm1);
        float a0 = exp2f(m0 - mn0), a1 = exp2f(m1 - mn1);
        m0 = mn0; m1 = mn1;

        // ---- p = exp2(s - m); sums + end buckets; classified
        float ps0 = 0.f, ps1 = 0.f, tl0 = 0.f, tl1 = 0.f, th0 = 0.f, th1 = 0.f;
        #pragma unroll
        for (int nt = 0; nt < 8; nt++) {
            int kg = k0 + nt * 8;
            if (kg >= qhi + 16) {                       // all -> high bucket
                #pragma unroll
                for (int e = 0; e < 4; e++) {
                    float p = exp2f(sa[nt][e] - ((e < 2) ? mn0 : mn1));
                    sa[nt][e] = p;
                    if (e < 2) { ps0 += p; th0 += p; }
                    else       { ps1 += p; th1 += p; }
                }
            } else if (kg + 7 <= qlo - 16) {            // all -> low bucket
                #pragma unroll
                for (int e = 0; e < 4; e++) {
                    float p = exp2f(sa[nt][e] - ((e < 2) ? mn0 : mn1));
                    sa[nt][e] = p;
                    if (e < 2) { ps0 += p; tl0 += p; }
                    else       { ps1 += p; tl1 += p; }
                }
            } else {
                int kc0 = kg + 2 * tig;
                #pragma unroll
                for (int e = 0; e < 4; e++) {
                    int kcol = kc0 + (e & 1);
                    float p = exp2f(sa[nt][e] - ((e < 2) ? mn0 : mn1));
                    sa[nt][e] = p;
                    int d = kcol - ((e < 2) ? qrow0 : qrow1);
                    if (e < 2) {
                        ps0 += p;
                        if (d <= -16) tl0 += p; else if (d >= 16) th0 += p;
                    } else {
                        ps1 += p;
                        if (d <= -16) tl1 += p; else if (d >= 16) th1 += p;
                    }
                }
            }
        }
        ps0 += __shfl_xor_sync(0xffffffffu, ps0, 1); ps0 += __shfl_xor_sync(0xffffffffu, ps0, 2);
        ps1 += __shfl_xor_sync(0xffffffffu, ps1, 1); ps1 += __shfl_xor_sync(0xffffffffu, ps1, 2);
        tl0 += __shfl_xor_sync(0xffffffffu, tl0, 1); tl0 += __shfl_xor_sync(0xffffffffu, tl0, 2);
        tl1 += __shfl_xor_sync(0xffffffffu, tl1, 1); tl1 += __shfl_xor_sync(0xffffffffu, tl1, 2);
        th0 += __shfl_xor_sync(0xffffffffu, th0, 1); th0 += __shfl_xor_sync(0xffffffffu, th0, 2);
        th1 += __shfl_xor_sync(0xffffffffu, th1, 1); th1 += __shfl_xor_sync(0xffffffffu, th1, 2);

        l0 = l0 * a0 + ps0;  l1 = l1 * a1 + ps1;
        eL0 = eL0 * a0 + tl0; eL1 = eL1 * a1 + tl1;
        eH0 = eH0 * a0 + th0; eH1 = eH1 * a1 + th1;

        #pragma unroll
        for (int nt = 0; nt < 8; nt++) {
            oa[nt][0] *= a0; oa[nt][1] *= a0;
            oa[nt][2] *= a1; oa[nt][3] *= a1;
        }

        // ---- wait V(t), PV with shuffle-P and ldmatrix V^T fragments
        if (t + 1 < KT) cp_wait<1>(); else cp_wait<0>();
        __syncthreads();

        const int L0 = (gid << 2) + (tig >> 1);
        const int L1 = L0 + 2;
        const bool odd = (tig & 1) != 0;
        #pragma unroll
        for (int kc = 0; kc < 8; kc++) {
            float a0e = __shfl_sync(0xffffffffu, sa[kc][0], L0);
            float a0o = __shfl_sync(0xffffffffu, sa[kc][1], L0);
            float a1e = __shfl_sync(0xffffffffu, sa[kc][2], L0);
            float a1o = __shfl_sync(0xffffffffu, sa[kc][3], L0);
            float a2e = __shfl_sync(0xffffffffu, sa[kc][0], L1);
            float a2o = __shfl_sync(0xffffffffu, sa[kc][1], L1);
            float a3e = __shfl_sync(0xffffffffu, sa[kc][2], L1);
            float a3o = __shfl_sync(0xffffffffu, sa[kc][3], L1);
            uint32_t p0 = f2tf(odd ? a0o : a0e);
            uint32_t p1 = f2tf(odd ? a1o : a1e);
            uint32_t p2 = f2tf(odd ? a2o : a2e);
            uint32_t p3 = f2tf(odd ? a3o : a3e);
            uint32_t vf[8][2];
            #pragma unroll
            for (int np = 0; np < 4; np++)
                ldsm4(vf[2*np][0], vf[2*np][1], vf[2*np+1][0], vf[2*np+1][1],
                      vBase[np] + kc * 32);
            #pragma unroll
            for (int nt = 0; nt < 8; nt++)
                mma8(oa[nt], p0, p1, p2, p3, vf[nt][0], vf[nt][1]);
        }
        __syncthreads();
    }

    // ---- epilogue ----
    const int b = bh >> 4, h = bh & 15;
    float il0 = 1.f / l0, il1 = 1.f / l1;

    if (tig == 0) {
        MR[wq + gid] = m0;     IL[wq + gid] = il0;
        MR[wq + gid + 8] = m1; IL[wq + gid + 8] = il1;
        SQ[(wq + gid) * NREL + 0]      = eL0 * il0;
        SQ[(wq + gid) * NREL + 32]     = eH0 * il0;
        SQ[(wq + gid + 8) * NREL + 0]  = eL1 * il1;
        SQ[(wq + gid + 8) * NREL + 32] = eH1 * il1;
    }
    for (int i = tid; i < NREL * 16; i += 128) {
        int row = i >> 4, c = i & 15;
        *reinterpret_cast<float4*>(&Vs[row * KS + 4 * c]) =
            reinterpret_cast<const float4*>(Ev)[i];
    }
    __syncthreads();

    for (int i = tid; i < 64 * 31; i += 128) {
        int row = i / 31, r = i % 31 + 1;
        SQ[row * NREL + r] = exp2f(SMID[row * NREL + r] - MR[row]) * IL[row];
    }
    __syncthreads();

    #pragma unroll
    for (int nt = 0; nt < 8; nt++) {
        oa[nt][0] *= il0; oa[nt][1] *= il0;
        oa[nt][2] *= il1; oa[nt][3] *= il1;
    }
    for (int r = 0; r < NREL; r++) {
        float pr0 = SQ[(wq + gid) * NREL + r];
        float pr1 = SQ[(wq + gid + 8) * NREL + r];
        #pragma unroll
        for (int nt = 0; nt < 8; nt++) {
            float2 ev = *reinterpret_cast<const float2*>(&Vs[r * KS + nt * 8 + 2 * tig]);
            oa[nt][0] += pr0 * ev.x; oa[nt][1] += pr0 * ev.y;
            oa[nt][2] += pr1 * ev.x; oa[nt][3] += pr1 * ev.y;
        }
    }
    #pragma unroll
    for (int nt = 0; nt < 8; nt++) {
        int col = h * HD + nt * 8 + 2 * tig;
        *reinterpret_cast<float2*>(&g_ctx[(size_t)(b * SEQ + qrow0) * DM + col]) =
            make_float2(f2tf_f(oa[nt][0]), f2tf_f(oa[nt][1]));
        *reinterpret_cast<float2*>(&g_ctx[(size_t)(b * SEQ + qrow1) * DM + col]) =
            make_float2(f2tf_f(oa[nt][2]), f2tf_f(oa[nt][3]));
    }
}

// ---------------- launch ------------------------------------------------------
extern "C" void kernel_launch(void* const* d_in, const int* in_sizes, int n_in,
                              void* d_out, int out_size)
{
    const float* queries = (const float*)d_in[0];
    const float* keys    = (const float*)d_in[1];
    const float* values  = (const float*)d_in[2];
    const int*   valid   = (const int*)  d_in[3];
    const float* Wq      = (const float*)d_in[4];
    const float* Wk      = (const float*)d_in[5];
    const float* Wv      = (const float*)d_in[6];
    const float* Wo      = (const float*)d_in[7];
    const float* Ek      = (const float*)d_in[8];
    const float* Ev      = (const float*)d_in[9];
    float* out = (float*)d_out;

    float *Qp, *Kp, *Vp, *Cp, *rw;
    cudaGetSymbolAddress((void**)&Qp, g_Q);
    cudaGetSymbolAddress((void**)&Kp, g_K);
    cudaGetSymbolAddress((void**)&Vp, g_V);
    cudaGetSymbolAddress((void**)&Cp, g_ctx);
    cudaGetSymbolAddress((void**)&rw, g_rw);

    const int M = BATCH * SEQ;          // 4096
    const size_t WN = (size_t)DM * DM;  // 1M

    const int smBig   = 2 * (128 * 36 + 128 * 36) * sizeof(float);   // 73728
    const int smFlash = (2 * 64 * 68 + 64 * 68
                         + 64 * NREL + 64 * NREL + 128) * sizeof(float); // 69632

    cudaFuncSetAttribute(gemm_big<true, true>,
        cudaFuncAttributeMaxDynamicSharedMemorySize, smBig);
    cudaFuncSetAttribute(gemm_big<false, false>,
        cudaFuncAttributeMaxDynamicSharedMemorySize, smBig);
    cudaFuncSetAttribute(flash_kernel,
        cudaFuncAttributeMaxDynamicSharedMemorySize, smFlash);

    // 1) pre-round WEIGHTS only
    ConvArgs ca;
    ca.src[0] = Wq; ca.src[1] = Wk; ca.src[2] = Wv; ca.src[3] = Wo;
    for (int i = 0; i < 4; i++) ca.dst[i] = rw + i * WN;
    ca.n4 = (int)(WN / 4);
    conv_kernel<<<dim3(128, 4), 256>>>(ca);

    // 2) Q/K/V projections; K/V vl-skip; V stored transposed
    Proj3Args pa;
    pa.A[0] = queries;      pa.A[1] = keys;         pa.A[2] = values;
    pa.B[0] = rw;           pa.B[1] = rw + WN;      pa.B[2] = rw + 2 * WN;
    pa.C[0] = Qp;           pa.C[1] = Kp;           pa.C[2] = Vp;
    gemm_big<true, true><<<dim3(DM / 128, M / 128, 3), 128, smBig>>>(
        pa, M, DM, DM, valid);

    // 3) fused attention
    flash_kernel<<<dim3(SEQ / 64, BH), 128, smFlash>>>(valid, Ek, Ev);

    // 4) out = ctx @ Wo^T
    Proj3Args po;
    po.A[0] = Cp; po.B[0] = rw + 3 * WN; po.C[0] = out;
    po.A[1] = po.A[2] = Cp; po.B[1] = po.B[2] = rw; po.C[1] = po.C[2] = out;
    gemm_big<false, false><<<dim3(DM / 128, M / 128, 1), 128, smBig>>>(
        po, M, DM, DM, nullptr);
}

// round 15
// speedup vs baseline: 1.3829x; 1.0256x over previous
#include <cuda_runtime.h>
#include <math.h>
#include <stdint.h>

#define BATCH 4
#define SEQ   1024
#define DM    1024
#define NH    16
#define HD    64
#define BH    (BATCH*NH)   // 64
#define NREL  33
#define SQP   41           // padded SQ row stride (bank-friendly, k-pad to 40)
#define NEGV  (-1e6f)
#define SCALE 0.1803368801111243f   // (1/sqrt(64)) * log2(e)

// ---------------- scratch (device globals: allocation is forbidden) ----------
__device__ float g_Q[BH*SEQ*HD];                 // [bh][s][d]  (tf32-rounded)
__device__ float g_K[BH*SEQ*HD];                 // [bh][s][d]
__device__ float g_V[BH*SEQ*HD];                 // [bh][d][s]  TRANSPOSED
__device__ float g_ctx[BATCH*SEQ*DM];            // merged-head ctx (tf32-rounded)
__device__ float g_rw [4u*1024*1024];            // pre-rounded Wq,Wk,Wv,Wo

// ---------------- helpers ----------------------------------------------------
__device__ __forceinline__ uint32_t f2tf(float f) {
    uint32_t u;
    asm("cvt.rna.tf32.f32 %0, %1;" : "=r"(u) : "f"(f));
    return u;
}
__device__ __forceinline__ float f2tf_f(float f) {
    return __uint_as_float(f2tf(f));
}
__device__ __forceinline__ uint32_t f2tf_u(uint32_t raw) {
    uint32_t u;
    asm("cvt.rna.tf32.f32 %0, %1;" : "=r"(u) : "f"(__uint_as_float(raw)));
    return u;
}
__device__ __forceinline__ void mma8(float* c,
    uint32_t a0, uint32_t a1, uint32_t a2, uint32_t a3,
    uint32_t b0, uint32_t b1)
{
    asm volatile(
        "mma.sync.aligned.m16n8k8.row.col.f32.tf32.tf32.f32 "
        "{%0,%1,%2,%3}, {%4,%5,%6,%7}, {%8,%9}, {%0,%1,%2,%3};"
        : "+f"(c[0]), "+f"(c[1]), "+f"(c[2]), "+f"(c[3])
        : "r"(a0), "r"(a1), "r"(a2), "r"(a3), "r"(b0), "r"(b1));
}
__device__ __forceinline__ void ldsm4(uint32_t& r0, uint32_t& r1,
                                      uint32_t& r2, uint32_t& r3, uint32_t addr)
{
    asm volatile("ldmatrix.sync.aligned.m8n8.x4.shared.b16 {%0,%1,%2,%3}, [%4];"
        : "=r"(r0), "=r"(r1), "=r"(r2), "=r"(r3) : "r"(addr));
}
__device__ __forceinline__ void cp16(void* smem_dst, const void* gmem_src) {
    uint32_t s = (uint32_t)__cvta_generic_to_shared(smem_dst);
    asm volatile("cp.async.cg.shared.global [%0], [%1], 16;\n"
                 :: "r"(s), "l"(gmem_src));
}
__device__ __forceinline__ void cp_commit() {
    asm volatile("cp.async.commit_group;\n");
}
template<int N>
__device__ __forceinline__ void cp_wait() {
    asm volatile("cp.async.wait_group %0;\n" :: "n"(N));
}
__device__ __forceinline__ uint32_t ldu(const float* p) {
    return __float_as_uint(*p);
}
__device__ __forceinline__ uint32_t smem_u32(const void* p) {
    return (uint32_t)__cvta_generic_to_shared(p);
}

// =============================================================================
// fp32 -> tf32-rounded fp32 copies (weights only)
// =============================================================================
struct ConvArgs {
    const float* src[4];
    float* dst[4];
    int n4;
};
__global__ void __launch_bounds__(256) conv_kernel(ConvArgs a)
{
    int rg = blockIdx.y;
    const float4* s = reinterpret_cast<const float4*>(a.src[rg]);
    float4* d = reinterpret_cast<float4*>(a.dst[rg]);
    for (int i = blockIdx.x * 256 + threadIdx.x; i < a.n4; i += gridDim.x * 256) {
        float4 v = s[i];
        v.x = f2tf_f(v.x); v.y = f2tf_f(v.y);
        v.z = f2tf_f(v.z); v.w = f2tf_f(v.w);
        d[i] = v;
    }
}

struct Proj3Args {
    const float* A[3];
    const float* B[3];
    float*       C[3];
};

// =============================================================================
// Big NT GEMM. PROJ3: z=1,2 (K,V) skip vl-dead row blocks; z=2 (V) stores
// TRANSPOSED [bh][d][s]. CVT_A: round A fragments post-ldmatrix.
// =============================================================================
template<bool PROJ3, bool CVT_A>
__global__ void __launch_bounds__(128, 3)
gemm_big(Proj3Args args, int M, int N, int K, const int* __restrict__ vlp)
{
    constexpr int BM = 128, BN = 128, BK = 32, T = 128;
    constexpr int ASZ = BM * (BK + 4);
    constexpr int ABYTES = ASZ * 4;
    constexpr int BBYTES = BN * (BK + 4) * 4;

    int z = PROJ3 ? blockIdx.z : 0;
    int m0 = blockIdx.y * BM, n0 = blockIdx.x * BN;

    if (PROJ3 && z > 0) {
        int b = m0 >> 10;
        int vlc = (vlp[b] + 63) & ~63;
        if ((m0 & 1023) >= vlc) return;
    }

    extern __shared__ float dynsmem[];
    float (*As)[BM][BK + 4] = reinterpret_cast<float(*)[BM][BK + 4]>(dynsmem);
    float (*Bs)[BN][BK + 4] = reinterpret_cast<float(*)[BN][BK + 4]>(dynsmem + 2 * ASZ);

    const float* A = args.A[z];
    const float* B = args.B[z];
    float*       C = args.C[z];

    int tid = threadIdx.x;
    int lane = tid & 31, warp = tid >> 5;
    int gid = lane >> 2, tig = lane & 3;
    int wm0 = (warp >> 1) * 64;
    int wn0 = (warp & 1) * 64;

    int Lm = lane >> 3, Lr = lane & 7;
    int a_row = ((Lm & 1) ? 8 : 0) + Lr;
    int a_col = (Lm & 2) ? 4 : 0;
    int b_row = ((Lm & 2) ? 8 : 0) + Lr;
    int b_col = (Lm & 1) ? 4 : 0;

    uint32_t sA = smem_u32(&As[0][0][0]);
    uint32_t sB = smem_u32(&Bs[0][0][0]);
    uint32_t aBase[4], bBase[4];
    #pragma unroll
    for (int mt = 0; mt < 4; mt++)
        aBase[mt] = sA + ((wm0 + mt * 16 + a_row) * (BK + 4) + a_col) * 4;
    #pragma unroll
    for (int np = 0; np < 4; np++)
        bBase[np] = sB + ((wn0 + np * 16 + b_row) * (BK + 4) + b_col) * 4;

    auto load_tiles = [&](int buf, int k0) {
        #pragma unroll
        for (int it = 0; it < 8; it++) {
            int idx = tid + it * T;
            int row = idx >> 3, kq = (idx & 7) << 2;
            cp16(&As[buf][row][kq], &A[(size_t)(m0 + row) * K + k0 + kq]);
        }
        #pragma unroll
        for (int it = 0; it < 8; it++) {
            int idx = tid + it * T;
            int row = idx >> 3, kq = (idx & 7) << 2;
            cp16(&Bs[buf][row][kq], &B[(size_t)(n0 + row) * K + k0 + kq]);
        }
        cp_commit();
    };

    float acc[4][8][4];
    #pragma unroll
    for (int i = 0; i < 4; i++)
        #pragma unroll
        for (int j = 0; j < 8; j++)
            #pragma unroll
            for (int l = 0; l < 4; l++) acc[i][j][l] = 0.f;

    const int KT = K / BK;
    load_tiles(0, 0);

    for (int kt = 0; kt < KT; kt++) {
        int buf = kt & 1;
        if (kt + 1 < KT) { load_tiles(buf ^ 1, (kt + 1) * BK); cp_wait<1>(); }
        else             { cp_wait<0>(); }
        __syncthreads();

        uint32_t aOff = buf * ABYTES;
        uint32_t bOff = buf * BBYTES;
        #pragma unroll
        for (int kc = 0; kc < BK / 8; kc++) {
            uint32_t kb4 = kc * 32;
            uint32_t af[4][4];
            #pragma unroll
            for (int mt = 0; mt < 4; mt++) {
                ldsm4(af[mt][0], af[mt][1], af[mt][2], af[mt][3],
                      aBase[mt] + aOff + kb4);
                if (CVT_A) {
                    af[mt][0] = f2tf_u(af[mt][0]);
                    af[mt][1] = f2tf_u(af[mt][1]);
                    af[mt][2] = f2tf_u(af[mt][2]);
                    af[mt][3] = f2tf_u(af[mt][3]);
                }
            }
            uint32_t bf[8][2];
            #pragma unroll
            for (int np = 0; np < 4; np++)
                ldsm4(bf[2*np][0], bf[2*np][1], bf[2*np+1][0], bf[2*np+1][1],
                      bBase[np] + bOff + kb4);
            #pragma unroll
            for (int mt = 0; mt < 4; mt++)
                #pragma unroll
                for (int nt = 0; nt < 8; nt++)
                    mma8(acc[mt][nt], af[mt][0], af[mt][1], af[mt][2], af[mt][3],
                         bf[nt][0], bf[nt][1]);
        }
        __syncthreads();
    }

    #pragma unroll
    for (int mt = 0; mt < 4; mt++) {
        #pragma unroll
        for (int nt = 0; nt < 8; nt++) {
            int r0 = m0 + wm0 + mt * 16 + gid;
            int c0 = n0 + wn0 + nt * 8 + 2 * tig;
            if (PROJ3) {
                int b = r0 >> 10, s = r0 & 1023, h = c0 >> 6, d = c0 & 63;
                float v0 = f2tf_f(acc[mt][nt][0]), v1 = f2tf_f(acc[mt][nt][1]);
                float v2 = f2tf_f(acc[mt][nt][2]), v3 = f2tf_f(acc[mt][nt][3]);
                if (z == 2) {
                    float* p = C + ((size_t)((b * NH + h) * HD + d)) * SEQ + s;
                    p[0] = v0;  p[SEQ] = v1;
                    p[8] = v2;  p[SEQ + 8] = v3;
                } else {
                    *reinterpret_cast<float2*>(
                        &C[(size_t)((b * NH + h) * SEQ + s) * HD + d]) =
                        make_float2(v0, v1);
                    *reinterpret_cast<float2*>(
                        &C[(size_t)((b * NH + h) * SEQ + s + 8) * HD + d]) =
                        make_float2(v2, v3);
                }
            } else {
                *reinterpret_cast<float2*>(&C[(size_t)r0 * N + c0]) =
                    make_float2(acc[mt][nt][0], acc[mt][nt][1]);
                *reinterpret_cast<float2*>(&C[(size_t)(r0 + 8) * N + c0]) =
                    make_float2(acc[mt][nt][2], acc[mt][nt][3]);
            }
        }
    }
}

// =============================================================================
// Fused flash attention: shuffle-P, ldmatrix K+V (V^T), band-classified
// softmax, and mma-based pe@Ev epilogue.
// =============================================================================
__global__ void __launch_bounds__(128, 3)
flash_kernel(const int* __restrict__ valid_lens,
             const float* __restrict__ Ek, const float* __restrict__ Ev)
{
    constexpr int KS = 68;
    constexpr int TILE = 64 * KS;
    constexpr int TILEB = TILE * 4;

    extern __shared__ float sm[];
    float* Ks = sm;                 // [2][64][68]  K rows [k][d]
    float* Vs = Ks + 2 * TILE;      // [64][68]     V^T rows [d][k]; Ek/Ev staging
    float* SQ = Vs + TILE;          // [64][41]     qek -> pe (cols 33..40 zero)
    float* SMID = SQ + 64 * SQP;    // [64][33]     raw mid-band scores
    float* MR = SMID + 64 * NREL;   // [64]
    float* IL = MR + 64;            // [64]

    const int q0 = blockIdx.x * 64;
    const int bh = blockIdx.y;
    const int vl  = valid_lens[bh >> 4];
    const int vlc = (vl + 63) & ~63;

    const int tid = threadIdx.x;
    const int lane = tid & 31, warp = tid >> 5;
    const int gid = lane >> 2, tig = lane & 3;
    const int wq = warp * 16;

    int Lm = lane >> 3, Lr = lane & 7;
    int b_row = ((Lm & 2) ? 8 : 0) + Lr;
    int b_col = (Lm & 1) ? 4 : 0;
    uint32_t sK = smem_u32(Ks);
    uint32_t sV = smem_u32(Vs);
    uint32_t kBase[4], vBase[4];
    #pragma unroll
    for (int np = 0; np < 4; np++) {
        kBase[np] = sK + ((np * 16 + b_row) * KS + b_col) * 4;
        vBase[np] = sV + ((np * 16 + b_row) * KS + b_col) * 4;
    }

    auto loadK = [&](int buf, int k0) {
        const float* Kg = g_K + ((size_t)bh * SEQ + k0) * HD;
        #pragma unroll
        for (int it = 0; it < 8; it++) {
            int idx = tid + it * 128;
            int row = idx >> 4, c4 = (idx & 15) << 2;
            cp16(&Ks[buf * TILE + row * KS + c4], Kg + row * HD + c4);
        }
        cp_commit();
    };
    auto loadV = [&](int k0) {
        const float* Vg = g_V + (size_t)bh * HD * SEQ + k0;
        #pragma unroll
        for (int it = 0; it < 8; it++) {
            int idx = tid + it * 128;
            int row = idx >> 4, c4 = (idx & 15) << 2;
            cp16(&Vs[row * KS + c4], Vg + (size_t)row * SEQ + c4);
        }
        cp_commit();
    };

    loadK(0, 0);

    // Ek -> Vs rows 0..32; zero SQ (cols 33..40 stay zero for the pe@Ev mma)
    for (int i = tid; i < NREL * 16; i += 128) {
        int row = i >> 4, c = i & 15;
        *reinterpret_cast<float4*>(&Vs[row * KS + 4 * c]) =
            reinterpret_cast<const float4*>(Ek)[i];
    }
    for (int i = tid; i < 64 * SQP; i += 128) SQ[i] = 0.f;

    uint32_t qa[8][4];
    {
        const float* Qg = g_Q + ((size_t)bh * SEQ + q0 + wq) * HD;
        #pragma unroll
        for (int kc = 0; kc < 8; kc++) {
            qa[kc][0] = ldu(&Qg[(size_t)gid       * HD + kc * 8 + tig]);
            qa[kc][1] = ldu(&Qg[(size_t)(gid + 8) * HD + kc * 8 + tig]);
            qa[kc][2] = ldu(&Qg[(size_t)gid       * HD + kc * 8 + tig + 4]);
            qa[kc][3] = ldu(&Qg[(size_t)(gid + 8) * HD + kc * 8 + tig + 4]);
        }
    }
    __syncthreads();    // Ek + SQ-zero visible

    {
        float sq[5][4];
        #pragma unroll
        for (int nt = 0; nt < 5; nt++)
            #pragma unroll
            for (int e = 0; e < 4; e++) sq[nt][e] = 0.f;
        #pragma unroll
        for (int kc = 0; kc < 8; kc++) {
            #pragma unroll
            for (int nt = 0; nt < 5; nt++) {
                uint32_t b0 = f2tf(Vs[(nt * 8 + gid) * KS + kc * 8 + tig]);
                uint32_t b1 = f2tf(Vs[(nt * 8 + gid) * KS + kc * 8 + tig + 4]);
                mma8(sq[nt], qa[kc][0], qa[kc][1], qa[kc][2], qa[kc][3], b0, b1);
            }
        }
        #pragma unroll
        for (int nt = 0; nt < 5; nt++) {
            #pragma unroll
            for (int e = 0; e < 4; e++) {
                int col = nt * 8 + 2 * tig + (e & 1);
                int row = wq + gid + ((e < 2) ? 0 : 8);
                if (col < NREL) SQ[row * SQP + col] = sq[nt][e];
            }
        }
    }
    for (int i = tid; i < 64 * NREL; i += 128) SMID[i] = NEGV;
    __syncthreads();

    const int qrow0 = q0 + wq + gid;
    const int qrow1 = qrow0 + 8;
    const int qlo = q0 + wq, qhi = qlo + 15;

    const float sqL0 = SQ[(wq + gid) * SQP + 0];
    const float sqH0 = SQ[(wq + gid) * SQP + 32];
    const float sqL1 = SQ[(wq + gid + 8) * SQP + 0];
    const float sqH1 = SQ[(wq + gid + 8) * SQP + 32];

    float oa[8][4];
    #pragma unroll
    for (int nt = 0; nt < 8; nt++)
        #pragma unroll
        for (int j = 0; j < 4; j++) oa[nt][j] = 0.f;

    float m0 = -1e30f, m1 = -1e30f;
    float l0 = 0.f, l1 = 0.f;
    float eL0 = 0.f, eL1 = 0.f, eH0 = 0.f, eH1 = 0.f;

    const int KT = vlc / 64;
    for (int t = 0; t < KT; t++) {
        int buf = t & 1;
        int k0 = t * 64;
        const bool last = (t == KT - 1);
        loadV(k0);
        if (t + 1 < KT) { loadK(buf ^ 1, k0 + 64); cp_wait<2>(); }
        else            { cp_wait<1>(); }
        __syncthreads();

        float sa[8][4];
        #pragma unroll
        for (int nt = 0; nt < 8; nt++)
            #pragma unroll
            for (int j = 0; j < 4; j++) sa[nt][j] = 0.f;

        uint32_t kOff = buf * TILEB;
        #pragma unroll
        for (int kc = 0; kc < 8; kc++) {
            uint32_t bf[8][2];
            #pragma unroll
            for (int np = 0; np < 4; np++)
                ldsm4(bf[2*np][0], bf[2*np][1], bf[2*np+1][0], bf[2*np+1][1],
                      kBase[np] + kOff + kc * 32);
            #pragma unroll
            for (int nt = 0; nt < 8; nt++)
                mma8(sa[nt], qa[kc][0], qa[kc][1], qa[kc][2], qa[kc][3],
                     bf[nt][0], bf[nt][1]);
        }

        float tm0 = -1e30f, tm1 = -1e30f;
        #pragma unroll
        for (int nt = 0; nt < 8; nt++) {
            int kg = k0 + nt * 8;
            if (kg >= qhi + 16) {
                #pragma unroll
                for (int e = 0; e < 4; e++) {
                    float s = (sa[nt][e] + ((e < 2) ? sqH0 : sqH1)) * SCALE;
                    if (last) {
                        int kcol = kg + 2 * tig + (e & 1);
                        if (kcol >= vl) s = NEGV;
                    }
                    sa[nt][e] = s;
                    if (e < 2) tm0 = fmaxf(tm0, s); else tm1 = fmaxf(tm1, s);
                }
            } else if (kg + 7 <= qlo - 16) {
                #pragma unroll
                for (int e = 0; e < 4; e++) {
                    float s = (sa[nt][e] + ((e < 2) ? sqL0 : sqL1)) * SCALE;
                    if (last) {
                        int kcol = kg + 2 * tig + (e & 1);
                        if (kcol >= vl) s = NEGV;
                    }
                    sa[nt][e] = s;
                    if (e < 2) tm0 = fmaxf(tm0, s); else tm1 = fmaxf(tm1, s);
                }
            } else {
                int kc0 = kg + 2 * tig;
                #pragma unroll
                for (int e = 0; e < 4; e++) {
                    int kcol = kc0 + (e & 1);
                    int qrow = (e < 2) ? qrow0 : qrow1;
                    int rloc = wq + gid + ((e < 2) ? 0 : 8);
                    int d = kcol - qrow;
                    int bidx = min(16, max(-16, d)) + 16;
                    float s = (sa[nt][e] + SQ[rloc * SQP + bidx]) * SCALE;
                    if (last && kcol >= vl) s = NEGV;
                    sa[nt][e] = s;
                    if (d > -16 && d < 16) SMID[rloc * NREL + bidx] = s;
                    if (e < 2) tm0 = fmaxf(tm0, s); else tm1 = fmaxf(tm1, s);
                }
            }
        }
        tm0 = fmaxf(tm0, __shfl_xor_sync(0xffffffffu, tm0, 1));
        tm0 = fmaxf(tm0, __shfl_xor_sync(0xffffffffu, tm0, 2));
        tm1 = fmaxf(tm1, __shfl_xor_sync(0xffffffffu, tm1, 1));
        tm1 = fmaxf(tm1, __shfl_xor_sync(0xffffffffu, tm1, 2));

        float mn0 = fmaxf(m0, tm0), mn1 = fmaxf(m1, tm1);
        float a0 = exp2f(m0 - mn0), a1 = exp2f(m1 - mn1);
        m0 = mn0; m1 = mn1;

        float ps0 = 0.f, ps1 = 0.f, tl0 = 0.f, tl1 = 0.f, th0 = 0.f, th1 = 0.f;
        #pragma unroll
        for (int nt = 0; nt < 8; nt++) {
            int kg = k0 + nt * 8;
            if (kg >= qhi + 16) {
                #pragma unroll
                for (int e = 0; e < 4; e++) {
                    float p = exp2f(sa[nt][e] - ((e < 2) ? mn0 : mn1));
                    sa[nt][e] = p;
                    if (e < 2) { ps0 += p; th0 += p; }
                    else       { ps1 += p; th1 += p; }
                }
            } else if (kg + 7 <= qlo - 16) {
                #pragma unroll
                for (int e = 0; e < 4; e++) {
                    float p = exp2f(sa[nt][e] - ((e < 2) ? mn0 : mn1));
                    sa[nt][e] = p;
                    if (e < 2) { ps0 += p; tl0 += p; }
                    else       { ps1 += p; tl1 += p; }
                }
            } else {
                int kc0 = kg + 2 * tig;
                #pragma unroll
                for (int e = 0; e < 4; e++) {
                    int kcol = kc0 + (e & 1);
                    float p = exp2f(sa[nt][e] - ((e < 2) ? mn0 : mn1));
                    sa[nt][e] = p;
                    int d = kcol - ((e < 2) ? qrow0 : qrow1);
                    if (e < 2) {
                        ps0 += p;
                        if (d <= -16) tl0 += p; else if (d >= 16) th0 += p;
                    } else {
                        ps1 += p;
                        if (d <= -16) tl1 += p; else if (d >= 16) th1 += p;
                    }
                }
            }
        }
        ps0 += __shfl_xor_sync(0xffffffffu, ps0, 1); ps0 += __shfl_xor_sync(0xffffffffu, ps0, 2);
        ps1 += __shfl_xor_sync(0xffffffffu, ps1, 1); ps1 += __shfl_xor_sync(0xffffffffu, ps1, 2);
        tl0 += __shfl_xor_sync(0xffffffffu, tl0, 1); tl0 += __shfl_xor_sync(0xffffffffu, tl0, 2);
        tl1 += __shfl_xor_sync(0xffffffffu, tl1, 1); tl1 += __shfl_xor_sync(0xffffffffu, tl1, 2);
        th0 += __shfl_xor_sync(0xffffffffu, th0, 1); th0 += __shfl_xor_sync(0xffffffffu, th0, 2);
        th1 += __shfl_xor_sync(0xffffffffu, th1, 1); th1 += __shfl_xor_sync(0xffffffffu, th1, 2);

        l0 = l0 * a0 + ps0;  l1 = l1 * a1 + ps1;
        eL0 = eL0 * a0 + tl0; eL1 = eL1 * a1 + tl1;
        eH0 = eH0 * a0 + th0; eH1 = eH1 * a1 + th1;

        #pragma unroll
        for (int nt = 0; nt < 8; nt++) {
            oa[nt][0] *= a0; oa[nt][1] *= a0;
            oa[nt][2] *= a1; oa[nt][3] *= a1;
        }

        if (t + 1 < KT) cp_wait<1>(); else cp_wait<0>();
        __syncthreads();

        const int L0 = (gid << 2) + (tig >> 1);
        const int L1 = L0 + 2;
        const bool odd = (tig & 1) != 0;
        #pragma unroll
        for (int kc = 0; kc < 8; kc++) {
            float a0e = __shfl_sync(0xffffffffu, sa[kc][0], L0);
            float a0o = __shfl_sync(0xffffffffu, sa[kc][1], L0);
            float a1e = __shfl_sync(0xffffffffu, sa[kc][2], L0);
            float a1o = __shfl_sync(0xffffffffu, sa[kc][3], L0);
            float a2e = __shfl_sync(0xffffffffu, sa[kc][0], L1);
            float a2o = __shfl_sync(0xffffffffu, sa[kc][1], L1);
            float a3e = __shfl_sync(0xffffffffu, sa[kc][2], L1);
            float a3o = __shfl_sync(0xffffffffu, sa[kc][3], L1);
            uint32_t p0 = f2tf(odd ? a0o : a0e);
            uint32_t p1 = f2tf(odd ? a1o : a1e);
            uint32_t p2 = f2tf(odd ? a2o : a2e);
            uint32_t p3 = f2tf(odd ? a3o : a3e);
            uint32_t vf[8][2];
            #pragma unroll
            for (int np = 0; np < 4; np++)
                ldsm4(vf[2*np][0], vf[2*np][1], vf[2*np+1][0], vf[2*np+1][1],
                      vBase[np] + kc * 32);
            #pragma unroll
            for (int nt = 0; nt < 8; nt++)
                mma8(oa[nt], p0, p1, p2, p3, vf[nt][0], vf[nt][1]);
        }
        __syncthreads();
    }

    // ---- epilogue ----
    const int b = bh >> 4, h = bh & 15;
    float il0 = 1.f / l0, il1 = 1.f / l1;

    if (tig == 0) {
        MR[wq + gid] = m0;     IL[wq + gid] = il0;
        MR[wq + gid + 8] = m1; IL[wq + gid + 8] = il1;
        SQ[(wq + gid) * SQP + 0]      = eL0 * il0;
        SQ[(wq + gid) * SQP + 32]     = eH0 * il0;
        SQ[(wq + gid + 8) * SQP + 0]  = eL1 * il1;
        SQ[(wq + gid + 8) * SQP + 32] = eH1 * il1;
    }
    // Ev -> Vs rows 0..32; zero rows 33..39 (k-padding for the pe@Ev mma)
    for (int i = tid; i < NREL * 16; i += 128) {
        int row = i >> 4, c = i & 15;
        *reinterpret_cast<float4*>(&Vs[row * KS + 4 * c]) =
            reinterpret_cast<const float4*>(Ev)[i];
    }
    for (int i = tid; i < 7 * 16; i += 128) {
        int row = 33 + (i >> 4), c = i & 15;
        *reinterpret_cast<float4*>(&Vs[row * KS + 4 * c]) =
            make_float4(0.f, 0.f, 0.f, 0.f);
    }
    __syncthreads();

    for (int i = tid; i < 64 * 31; i += 128) {
        int row = i / 31, r = i % 31 + 1;
        SQ[row * SQP + r] = exp2f(SMID[row * NREL + r] - MR[row]) * IL[row];
    }
    __syncthreads();    // pe (SQ) + Ev (Vs) ready

    // normalize O, then oa += pe @ Ev via tf32 mma (k padded to 40)
    #pragma unroll
    for (int nt = 0; nt < 8; nt++) {
        oa[nt][0] *= il0; oa[nt][1] *= il0;
        oa[nt][2] *= il1; oa[nt][3] *= il1;
    }
    #pragma unroll
    for (int kc = 0; kc < 5; kc++) {
        int kb = kc * 8;
        uint32_t a0 = f2tf(SQ[(wq + gid)     * SQP + kb + tig]);
        uint32_t a1 = f2tf(SQ[(wq + gid + 8) * SQP + kb + tig]);
        uint32_t a2 = f2tf(SQ[(wq + gid)     * SQP + kb + tig + 4]);
        uint32_t a3 = f2tf(SQ[(wq + gid + 8) * SQP + kb + tig + 4]);
        #pragma unroll
        for (int nt = 0; nt < 8; nt++) {
            int cn = nt * 8 + gid;
            uint32_t b0 = f2tf(Vs[(kb + tig)     * KS + cn]);
            uint32_t b1 = f2tf(Vs[(kb + tig + 4) * KS + cn]);
            mma8(oa[nt], a0, a1, a2, a3, b0, b1);
        }
    }
    #pragma unroll
    for (int nt = 0; nt < 8; nt++) {
        int col = h * HD + nt * 8 + 2 * tig;
        *reinterpret_cast<float2*>(&g_ctx[(size_t)(b * SEQ + qrow0) * DM + col]) =
            make_float2(f2tf_f(oa[nt][0]), f2tf_f(oa[nt][1]));
        *reinterpret_cast<float2*>(&g_ctx[(size_t)(b * SEQ + qrow1) * DM + col]) =
            make_float2(f2tf_f(oa[nt][2]), f2tf_f(oa[nt][3]));
    }
}

// ---------------- launch ------------------------------------------------------
extern "C" void kernel_launch(void* const* d_in, const int* in_sizes, int n_in,
                              void* d_out, int out_size)
{
    const float* queries = (const float*)d_in[0];
    const float* keys    = (const float*)d_in[1];
    const float* values  = (const float*)d_in[2];
    const int*   valid   = (const int*)  d_in[3];
    const float* Wq      = (const float*)d_in[4];
    const float* Wk      = (const float*)d_in[5];
    const float* Wv      = (const float*)d_in[6];
    const float* Wo      = (const float*)d_in[7];
    const float* Ek      = (const float*)d_in[8];
    const float* Ev      = (const float*)d_in[9];
    float* out = (float*)d_out;

    float *Qp, *Kp, *Vp, *Cp, *rw;
    cudaGetSymbolAddress((void**)&Qp, g_Q);
    cudaGetSymbolAddress((void**)&Kp, g_K);
    cudaGetSymbolAddress((void**)&Vp, g_V);
    cudaGetSymbolAddress((void**)&Cp, g_ctx);
    cudaGetSymbolAddress((void**)&rw, g_rw);

    const int M = BATCH * SEQ;          // 4096
    const size_t WN = (size_t)DM * DM;  // 1M

    const int smBig   = 2 * (128 * 36 + 128 * 36) * sizeof(float);   // 73728
    const int smFlash = (2 * 64 * 68 + 64 * 68 + 64 * SQP
                         + 64 * NREL + 128) * sizeof(float);         // 71680

    cudaFuncSetAttribute(gemm_big<true, true>,
        cudaFuncAttributeMaxDynamicSharedMemorySize, smBig);
    cudaFuncSetAttribute(gemm_big<false, false>,
        cudaFuncAttributeMaxDynamicSharedMemorySize, smBig);
    cudaFuncSetAttribute(flash_kernel,
        cudaFuncAttributeMaxDynamicSharedMemorySize, smFlash);

    // 1) pre-round WEIGHTS only
    ConvArgs ca;
    ca.src[0] = Wq; ca.src[1] = Wk; ca.src[2] = Wv; ca.src[3] = Wo;
    for (int i = 0; i < 4; i++) ca.dst[i] = rw + i * WN;
    ca.n4 = (int)(WN / 4);
    conv_kernel<<<dim3(128, 4), 256>>>(ca);

    // 2) Q/K/V projections; K/V vl-skip; V stored transposed
    Proj3Args pa;
    pa.A[0] = queries;      pa.A[1] = keys;         pa.A[2] = values;
    pa.B[0] = rw;           pa.B[1] = rw + WN;      pa.B[2] = rw + 2 * WN;
    pa.C[0] = Qp;           pa.C[1] = Kp;           pa.C[2] = Vp;
    gemm_big<true, true><<<dim3(DM / 128, M / 128, 3), 128, smBig>>>(
        pa, M, DM, DM, valid);

    // 3) fused attention
    flash_kernel<<<dim3(SEQ / 64, BH), 128, smFlash>>>(valid, Ek, Ev);

    // 4) out = ctx @ Wo^T
    Proj3Args po;
    po.A[0] = Cp; po.B[0] = rw + 3 * WN; po.C[0] = out;
    po.A[1] = po.A[2] = Cp; po.B[1] = po.B[2] = rw; po.C[1] = po.C[2] = out;
    gemm_big<false, false><<<dim3(DM / 128, M / 128, 1), 128, smBig>>>(
        po, M, DM, DM, nullptr);
}